// round 13
// baseline (speedup 1.0000x reference)
#include <cuda_runtime.h>

#define NG   8192
#define HH   256
#define WW   256
#define HWP  (HH*WW)

// ---------------- device scratch (no allocations allowed) ----------------
__device__ unsigned long long g_bufA[NG];   // (sortable_key32 << 16) | idx16
__device__ unsigned long long g_bufB[NG];
__device__ float4 g_pre [NG*3];             // unsorted packed gaussians
__device__ float4 g_pack[NG*3];             // depth-sorted packed gaussians
__device__ float4 g_cull[NG];               // sorted cull vectors (ux, uy, ex, ey)
__device__ unsigned short g_list[256*NG];   // per-tile depth-ordered index lists (4MB)
__device__ int g_cnt[256];                  // per-tile list lengths

// pack layout per gaussian (3 float4):
//  [0] = (ux, uy, cinv_a, cinv_b)
//  [1] = (cinv_c, alpha, ex, ey)     ex/ey = conservative bbox half-extents (px); -1e30 => culled
//  [2] = (colR, colG, colB, 0)

// ---------------- 1. per-gaussian preprocess ----------------
__global__ void preprocess_kernel(const float* __restrict__ pws,
                                  const float* __restrict__ shs,
                                  const float* __restrict__ alphas_raw,
                                  const float* __restrict__ scales_raw,
                                  const float* __restrict__ rots_raw,
                                  const float* __restrict__ Rcw,
                                  const float* __restrict__ tcw,
                                  const float* __restrict__ intr,
                                  float* __restrict__ areas)
{
    int n = blockIdx.x * blockDim.x + threadIdx.x;
    if (n >= NG) return;

    const float fx = intr[0], fy = intr[1], cx = intr[2], cy = intr[3];
    const float R00 = Rcw[0], R01 = Rcw[1], R02 = Rcw[2];
    const float R10 = Rcw[3], R11 = Rcw[4], R12 = Rcw[5];
    const float R20 = Rcw[6], R21 = Rcw[7], R22 = Rcw[8];
    const float t0 = tcw[0], t1 = tcw[1], t2 = tcw[2];

    const float pwx = pws[3*n+0], pwy = pws[3*n+1], pwz = pws[3*n+2];

    // camera-space point
    const float pcx = R00*pwx + R01*pwy + R02*pwz + t0;
    const float pcy = R10*pwx + R11*pwy + R12*pwz + t1;
    const float pcz = R20*pwx + R21*pwy + R22*pwz + t2;
    const float depth = pcz;
    const float zs = (depth > 0.2f) ? depth : 1.0f;
    const float iz = 1.0f / zs;

    const float ux = fx * pcx * iz + cx;
    const float uy = fy * pcy * iz + cy;

    // activations
    const float alpha = 1.0f / (1.0f + expf(-alphas_raw[n]));
    const float sx = expf(scales_raw[3*n+0]);
    const float sy = expf(scales_raw[3*n+1]);
    const float sz = expf(scales_raw[3*n+2]);

    float qw = rots_raw[4*n+0], qx = rots_raw[4*n+1], qy = rots_raw[4*n+2], qz = rots_raw[4*n+3];
    {
        const float qn = sqrtf(qw*qw + qx*qx + qy*qy + qz*qz);
        const float qi = 1.0f / qn;
        qw *= qi; qx *= qi; qy *= qi; qz *= qi;
    }
    // rotation matrix
    const float r00 = 1.0f - 2.0f*(qy*qy + qz*qz), r01 = 2.0f*(qx*qy - qw*qz), r02 = 2.0f*(qx*qz + qw*qy);
    const float r10 = 2.0f*(qx*qy + qw*qz), r11 = 1.0f - 2.0f*(qx*qx + qz*qz), r12 = 2.0f*(qy*qz - qw*qx);
    const float r20 = 2.0f*(qx*qz - qw*qy), r21 = 2.0f*(qy*qz + qw*qx), r22 = 1.0f - 2.0f*(qx*qx + qy*qy);

    // M = R * diag(scales); cov3d = M M^T (symmetric 6)
    const float m00 = r00*sx, m01 = r01*sy, m02 = r02*sz;
    const float m10 = r10*sx, m11 = r11*sy, m12 = r12*sz;
    const float m20 = r20*sx, m21 = r21*sy, m22 = r22*sz;
    const float V00 = m00*m00 + m01*m01 + m02*m02;
    const float V01 = m00*m10 + m01*m11 + m02*m12;
    const float V02 = m00*m20 + m01*m21 + m02*m22;
    const float V11 = m10*m10 + m11*m11 + m12*m12;
    const float V12 = m10*m20 + m11*m21 + m12*m22;
    const float V22 = m20*m20 + m21*m21 + m22*m22;

    // Jacobian and T = J @ Rcw
    const float tanfx = WW / (2.0f * fx);
    const float tanfy = HH / (2.0f * fy);
    const float xn = pcx * iz, yn = pcy * iz;
    const float txl = fminf(fmaxf(xn, -1.3f*tanfx), 1.3f*tanfx) * zs;
    const float tyl = fminf(fmaxf(yn, -1.3f*tanfy), 1.3f*tanfy) * zs;
    const float iz2 = iz * iz;
    const float J00 = fx * iz, J02 = -fx * txl * iz2;
    const float J11 = fy * iz, J12 = -fy * tyl * iz2;
    const float T00 = J00*R00 + J02*R20;
    const float T01 = J00*R01 + J02*R21;
    const float T02 = J00*R02 + J02*R22;
    const float T10 = J11*R10 + J12*R20;
    const float T11 = J11*R11 + J12*R21;
    const float T12 = J11*R12 + J12*R22;

    // cov2d = T V T^T + 0.3 I
    const float v0 = V00*T00 + V01*T01 + V02*T02;
    const float v1 = V01*T00 + V11*T01 + V12*T02;
    const float v2 = V02*T00 + V12*T01 + V22*T02;
    const float w0 = V00*T10 + V01*T11 + V02*T12;
    const float w1 = V01*T10 + V11*T11 + V12*T12;
    const float w2 = V02*T10 + V12*T11 + V22*T12;
    const float a = T00*v0 + T01*v1 + T02*v2 + 0.3f;
    const float b = T00*w0 + T01*w1 + T02*w2;
    const float c = T10*w0 + T11*w1 + T12*w2 + 0.3f;

    const float det = a*c - b*b;
    const bool valid = (depth > 0.2f) && (det > 0.0f);
    const float det_s = valid ? det : 1.0f;
    const float invd = 1.0f / det_s;
    const float ca = c * invd;
    const float cb = -b * invd;
    const float cc = a * invd;

    const float mid = 0.5f * (a + c);
    const float lam = mid + sqrtf(fmaxf(mid*mid - det, 0.1f));
    const float radius = valid ? ceilf(3.0f * sqrtf(lam)) : 0.0f;
    areas[2*n+0] = radius;
    areas[2*n+1] = radius;

    // view direction (twc = -Rcw^T tcw)
    const float twcx = -(R00*t0 + R10*t1 + R20*t2);
    const float twcy = -(R01*t0 + R11*t1 + R21*t2);
    const float twcz = -(R02*t0 + R12*t1 + R22*t2);
    float dxn = pwx - twcx, dyn = pwy - twcy, dzn = pwz - twcz;
    const float dinv = 1.0f / sqrtf(dxn*dxn + dyn*dyn + dzn*dzn);
    const float X = dxn*dinv, Y = dyn*dinv, Z = dzn*dinv;
    const float XX = X*X, YY = Y*Y, ZZ = Z*Z, XY = X*Y, YZ = Y*Z, XZ = X*Z;

    const float* sh = shs + n*48;
    float col[3];
#pragma unroll
    for (int ch = 0; ch < 3; ch++) {
        float res =  0.28209479177387814f * sh[0*3+ch];
        res += -0.4886025119029199f  * Y * sh[1*3+ch];
        res +=  0.4886025119029199f  * Z * sh[2*3+ch];
        res += -0.4886025119029199f  * X * sh[3*3+ch];
        res +=  1.0925484305920792f  * XY * sh[4*3+ch];
        res += -1.0925484305920792f  * YZ * sh[5*3+ch];
        res +=  0.31539156525252005f * (2.0f*ZZ - XX - YY) * sh[6*3+ch];
        res += -1.0925484305920792f  * XZ * sh[7*3+ch];
        res +=  0.5462742152960396f  * (XX - YY) * sh[8*3+ch];
        res += -0.5900435899266435f  * Y * (3.0f*XX - YY) * sh[9*3+ch];
        res +=  2.890611442640554f   * XY * Z * sh[10*3+ch];
        res += -0.4570457994644658f  * Y * (4.0f*ZZ - XX - YY) * sh[11*3+ch];
        res +=  0.3731763325901154f  * Z * (2.0f*ZZ - 3.0f*XX - 3.0f*YY) * sh[12*3+ch];
        res += -0.4570457994644658f  * X * (4.0f*ZZ - XX - YY) * sh[13*3+ch];
        res +=  1.445305721320277f   * Z * (XX - YY) * sh[14*3+ch];
        res += -0.5900435899266435f  * X * (XX - 3.0f*YY) * sh[15*3+ch];
        col[ch] = fmaxf(res + 0.5f, 0.0f);
    }

    // conservative support half-extents: alp >= 1/255 requires Q <= ln(255*alpha)
    const float tthr = logf(255.0f * alpha);
    float ex, ey;
    if (valid && tthr > 0.0f) {
        ex = sqrtf(2.0f * tthr * a) + 1.0f;   // +1px safety margin
        ey = sqrtf(2.0f * tthr * c) + 1.0f;
    } else {
        ex = -1e30f; ey = -1e30f;             // never overlaps any tile
    }

    g_pre[n*3+0] = make_float4(ux, uy, ca, cb);
    g_pre[n*3+1] = make_float4(cc, alpha, ex, ey);
    g_pre[n*3+2] = make_float4(col[0], col[1], col[2], 0.0f);

    // sortable key: float -> monotone uint, packed with index for a unique stable key
    unsigned ub = __float_as_uint(depth);
    ub = (ub & 0x80000000u) ? ~ub : (ub | 0x80000000u);
    g_bufA[n] = ((unsigned long long)ub << 16) | (unsigned)n;
}

// ---------------- 2. depth argsort: single-CTA 4x8-bit LSD radix, stable ----------------
// (config-A version: shared atomicAdd histograms — measured fastest variant)
__global__ void __launch_bounds__(1024) sort_kernel()
{
    __shared__ unsigned hist[32][256];   // per-warp digit counts -> running scatter offsets
    __shared__ unsigned dbase[256];      // digit totals -> exclusive digit bases

    const int tid  = threadIdx.x;
    const int wid  = tid >> 5;
    const int lane = tid & 31;
    const unsigned FULL = 0xffffffffu;

    unsigned long long* src = g_bufA;
    unsigned long long* dst = g_bufB;

#pragma unroll
    for (int pass = 0; pass < 4; pass++) {
        const int shift = 16 + 8 * pass;

        // zero per-warp histograms
        for (int i = tid; i < 32 * 256; i += 1024)
            ((unsigned*)hist)[i] = 0u;
        __syncthreads();

        // load 8 elements per thread; element order = (wid, slot, lane) ascending
        unsigned long long v[8];
        int d[8];
#pragma unroll
        for (int s = 0; s < 8; s++) {
            v[s] = src[wid * 256 + s * 32 + lane];
            d[s] = (int)((v[s] >> shift) & 255u);
        }
        // per-warp histogram (private row: no cross-warp contention; spread ATOMS ~LSU floor)
#pragma unroll
        for (int s = 0; s < 8; s++)
            atomicAdd(&hist[wid][d[s]], 1u);
        __syncthreads();

        // digit totals
        if (tid < 256) {
            unsigned tot = 0;
#pragma unroll
            for (int w = 0; w < 32; w++) tot += hist[w][tid];
            dbase[tid] = tot;
        }
        __syncthreads();

        // exclusive scan of 256 digit totals (warp 0, 8 values per lane)
        if (tid < 32) {
            unsigned x[8], e[8], s = 0;
#pragma unroll
            for (int k = 0; k < 8; k++) { x[k] = dbase[tid * 8 + k]; e[k] = s; s += x[k]; }
            unsigned inc = s;
#pragma unroll
            for (int off = 1; off < 32; off <<= 1) {
                unsigned nval = __shfl_up_sync(FULL, inc, off);
                if (lane >= off) inc += nval;
            }
            const unsigned wexcl = inc - s;
#pragma unroll
            for (int k = 0; k < 8; k++) dbase[tid * 8 + k] = wexcl + e[k];
        }
        __syncthreads();

        // convert per-warp counts into absolute running start offsets (warp-major stable)
        if (tid < 256) {
            unsigned running = dbase[tid];
#pragma unroll
            for (int w = 0; w < 32; w++) {
                unsigned tmp = hist[w][tid];
                hist[w][tid] = running;
                running += tmp;
            }
        }
        __syncthreads();

        // stable scatter, slot by slot (slot order preserves intra-thread order)
#pragma unroll
        for (int s = 0; s < 8; s++) {
            const unsigned peers  = __match_any_sync(FULL, d[s]);
            const unsigned rank   = __popc(peers & ((1u << lane) - 1u));
            const int      leader = __ffs(peers) - 1;
            unsigned base_o = 0;
            if (lane == leader) base_o = hist[wid][d[s]];
            base_o = __shfl_sync(FULL, base_o, leader);
            dst[base_o + rank] = v[s];
            if (lane == leader) hist[wid][d[s]] = base_o + __popc(peers);
        }
        __syncthreads();   // dst (global) visible to block before next pass reads it

        unsigned long long* t = src; src = dst; dst = t;
    }
    // 4 passes: A->B->A->B->A : final sorted sequence lives in g_bufA
}

// ---------------- 3. gather into sorted order ----------------
__global__ void gather_kernel()
{
    const int s = blockIdx.x * blockDim.x + threadIdx.x;
    if (s < NG) {
        const int g = (int)(g_bufA[s] & 0xFFFFu);
        const float4 p0 = g_pre[g*3+0];
        const float4 p1 = g_pre[g*3+1];
        g_pack[s*3+0] = p0;
        g_pack[s*3+1] = p1;
        g_pack[s*3+2] = g_pre[g*3+2];
        g_cull[s] = make_float4(p0.x, p0.y, p1.z, p1.w);   // (ux, uy, ex, ey)
    }
}

// ---------------- 4. tile binning: one warp per 16x16 tile, order-preserving -----------
__global__ void __launch_bounds__(256) binning_kernel()
{
    const int wid  = threadIdx.x >> 5;
    const int lane = threadIdx.x & 31;
    const int t = blockIdx.x * 8 + wid;            // 32 CTAs x 8 warps = 256 tiles
    const float tx0 = (float)((t & 15) * 16), tx1 = tx0 + 15.0f;
    const float ty0 = (float)((t >> 4) * 16), ty1 = ty0 + 15.0f;

    unsigned short* lst = g_list + t * NG;
    int cnt = 0;
    for (int i = 0; i < NG; i += 32) {
        const float4 cv = g_cull[i + lane];
        const bool keep = (cv.x - cv.z <= tx1) && (cv.x + cv.z >= tx0) &&
                          (cv.y - cv.w <= ty1) && (cv.y + cv.w >= ty0);
        const unsigned m = __ballot_sync(0xffffffffu, keep);
        if (keep)
            lst[cnt + __popc(m & ((1u << lane) - 1u))] = (unsigned short)(i + lane);
        cnt += __popc(m);
    }
    if (lane == 0) g_cnt[t] = cnt;
}

// ---------------- 5. tiled compositing over per-tile lists ----------------
__global__ void __launch_bounds__(256) render_kernel(float* __restrict__ out)
{
    __shared__ float4 s0[256];
    __shared__ float4 s1[256];
    __shared__ float  s2[256];

    const int tid = threadIdx.x;
    const int t = blockIdx.x;                       // tile id
    const int x = (t & 15) * 16 + (tid & 15);
    const int y = (t >> 4) * 16 + (tid >> 4);
    const float px = (float)x, py = (float)y;

    const unsigned short* lst = g_list + t * NG;
    const int nlist = g_cnt[t];

    float T = 1.0f, ar = 0.0f, ag = 0.0f, ab = 0.0f;
    int done = 0;

    for (int base = 0; base < nlist; base += 256) {
        const int n = min(256, nlist - base);
        if (tid < n) {
            const int idx = (int)lst[base + tid];
            const float4 p0 = g_pack[idx*3+0];      // (ux, uy, ca, cb)
            const float4 p1 = g_pack[idx*3+1];      // (cc, alpha, ex, ey)
            const float4 p2 = g_pack[idx*3+2];      // (r, g, b, 0)
            s0[tid] = p0;
            s1[tid] = make_float4(p1.x, p1.y, p2.x, p2.y);   // (cc, alpha, r, g)
            s2[tid] = p2.z;                                  // b
        }
        __syncthreads();                            // compaction visible before reads

        if (!done) {
            for (int i = 0; i < n; i++) {
                const float4 q0 = s0[i];
                const float4 q1 = s1[i];
                const float dx = px - q0.x;
                const float dy = py - q0.y;
                const float pw = -0.5f*(q0.z*dx*dx + q1.x*dy*dy) - q0.w*dx*dy;
                if (pw > 0.0f) continue;
                const float alp = fminf(0.99f, q1.y * __expf(pw));
                if (alp < (1.0f/255.0f)) continue;
                const float wgt = alp * T;
                ar += wgt * q1.z;
                ag += wgt * q1.w;
                ab += wgt * s2[i];
                T *= (1.0f - alp);
                if (T <= 1e-4f) { done = 1; break; }
            }
        }
        // consensus early-exit; also orders this chunk's reads before next chunk's writes
        if (__syncthreads_and(done)) break;
    }

    const int p = y * WW + x;
    out[p]         = ar;
    out[HWP + p]   = ag;
    out[2*HWP + p] = ab;
}

// ---------------- launch ----------------
extern "C" void kernel_launch(void* const* d_in, const int* in_sizes, int n_in,
                              void* d_out, int out_size)
{
    const float* pws        = (const float*)d_in[0];
    const float* shs        = (const float*)d_in[1];
    const float* alphas_raw = (const float*)d_in[2];
    const float* scales_raw = (const float*)d_in[3];
    const float* rots_raw   = (const float*)d_in[4];
    // d_in[5] = us (forward no-op)
    const float* Rcw        = (const float*)d_in[6];
    const float* tcw        = (const float*)d_in[7];
    const float* intr       = (const float*)d_in[8];
    float* out = (float*)d_out;

    preprocess_kernel<<<(NG + 255) / 256, 256>>>(pws, shs, alphas_raw, scales_raw, rots_raw,
                                                 Rcw, tcw, intr, out + 3 * HWP);
    sort_kernel<<<1, 1024>>>();
    gather_kernel<<<(NG + 255) / 256, 256>>>();
    binning_kernel<<<32, 256>>>();
    render_kernel<<<256, 256>>>(out);
}

// round 14
// speedup vs baseline: 1.5028x; 1.5028x over previous
#include <cuda_runtime.h>

#define NG   8192
#define HH   256
#define WW   256
#define HWP  (HH*WW)

// ---------------- device scratch (no allocations allowed) ----------------
__device__ unsigned long long g_bufA[NG];   // (sortable_key32 << 16) | idx16
__device__ unsigned long long g_bufB[NG];
__device__ float4 g_pre [NG*3];             // unsorted packed gaussians
__device__ float4 g_pack[NG*3];             // depth-sorted packed gaussians
__device__ float4 g_cull[NG];               // sorted cull vectors (ux, uy, ex, ey)
__device__ unsigned short g_list[256*NG];   // per-tile depth-ordered index lists (4MB)
__device__ int g_cnt[256];                  // per-tile list lengths

// pack layout per gaussian (3 float4):
//  [0] = (ux, uy, cinv_a, cinv_b)
//  [1] = (cinv_c, alpha, ex, ey)     ex/ey = conservative bbox half-extents (px); -1e30 => culled
//  [2] = (colR, colG, colB, 0)

// ---------------- 1. per-gaussian preprocess ----------------
__global__ void preprocess_kernel(const float* __restrict__ pws,
                                  const float* __restrict__ shs,
                                  const float* __restrict__ alphas_raw,
                                  const float* __restrict__ scales_raw,
                                  const float* __restrict__ rots_raw,
                                  const float* __restrict__ Rcw,
                                  const float* __restrict__ tcw,
                                  const float* __restrict__ intr,
                                  float* __restrict__ areas)
{
    int n = blockIdx.x * blockDim.x + threadIdx.x;
    if (n >= NG) return;

    const float fx = intr[0], fy = intr[1], cx = intr[2], cy = intr[3];
    const float R00 = Rcw[0], R01 = Rcw[1], R02 = Rcw[2];
    const float R10 = Rcw[3], R11 = Rcw[4], R12 = Rcw[5];
    const float R20 = Rcw[6], R21 = Rcw[7], R22 = Rcw[8];
    const float t0 = tcw[0], t1 = tcw[1], t2 = tcw[2];

    const float pwx = pws[3*n+0], pwy = pws[3*n+1], pwz = pws[3*n+2];

    // camera-space point
    const float pcx = R00*pwx + R01*pwy + R02*pwz + t0;
    const float pcy = R10*pwx + R11*pwy + R12*pwz + t1;
    const float pcz = R20*pwx + R21*pwy + R22*pwz + t2;
    const float depth = pcz;
    const float zs = (depth > 0.2f) ? depth : 1.0f;
    const float iz = 1.0f / zs;

    const float ux = fx * pcx * iz + cx;
    const float uy = fy * pcy * iz + cy;

    // activations
    const float alpha = 1.0f / (1.0f + expf(-alphas_raw[n]));
    const float sx = expf(scales_raw[3*n+0]);
    const float sy = expf(scales_raw[3*n+1]);
    const float sz = expf(scales_raw[3*n+2]);

    float qw = rots_raw[4*n+0], qx = rots_raw[4*n+1], qy = rots_raw[4*n+2], qz = rots_raw[4*n+3];
    {
        const float qn = sqrtf(qw*qw + qx*qx + qy*qy + qz*qz);
        const float qi = 1.0f / qn;
        qw *= qi; qx *= qi; qy *= qi; qz *= qi;
    }
    // rotation matrix
    const float r00 = 1.0f - 2.0f*(qy*qy + qz*qz), r01 = 2.0f*(qx*qy - qw*qz), r02 = 2.0f*(qx*qz + qw*qy);
    const float r10 = 2.0f*(qx*qy + qw*qz), r11 = 1.0f - 2.0f*(qx*qx + qz*qz), r12 = 2.0f*(qy*qz - qw*qx);
    const float r20 = 2.0f*(qx*qz - qw*qy), r21 = 2.0f*(qy*qz + qw*qx), r22 = 1.0f - 2.0f*(qx*qx + qy*qy);

    // M = R * diag(scales); cov3d = M M^T (symmetric 6)
    const float m00 = r00*sx, m01 = r01*sy, m02 = r02*sz;
    const float m10 = r10*sx, m11 = r11*sy, m12 = r12*sz;
    const float m20 = r20*sx, m21 = r21*sy, m22 = r22*sz;
    const float V00 = m00*m00 + m01*m01 + m02*m02;
    const float V01 = m00*m10 + m01*m11 + m02*m12;
    const float V02 = m00*m20 + m01*m21 + m02*m22;
    const float V11 = m10*m10 + m11*m11 + m12*m12;
    const float V12 = m10*m20 + m11*m21 + m12*m22;
    const float V22 = m20*m20 + m21*m21 + m22*m22;

    // Jacobian and T = J @ Rcw
    const float tanfx = WW / (2.0f * fx);
    const float tanfy = HH / (2.0f * fy);
    const float xn = pcx * iz, yn = pcy * iz;
    const float txl = fminf(fmaxf(xn, -1.3f*tanfx), 1.3f*tanfx) * zs;
    const float tyl = fminf(fmaxf(yn, -1.3f*tanfy), 1.3f*tanfy) * zs;
    const float iz2 = iz * iz;
    const float J00 = fx * iz, J02 = -fx * txl * iz2;
    const float J11 = fy * iz, J12 = -fy * tyl * iz2;
    const float T00 = J00*R00 + J02*R20;
    const float T01 = J00*R01 + J02*R21;
    const float T02 = J00*R02 + J02*R22;
    const float T10 = J11*R10 + J12*R20;
    const float T11 = J11*R11 + J12*R21;
    const float T12 = J11*R12 + J12*R22;

    // cov2d = T V T^T + 0.3 I
    const float v0 = V00*T00 + V01*T01 + V02*T02;
    const float v1 = V01*T00 + V11*T01 + V12*T02;
    const float v2 = V02*T00 + V12*T01 + V22*T02;
    const float w0 = V00*T10 + V01*T11 + V02*T12;
    const float w1 = V01*T10 + V11*T11 + V12*T12;
    const float w2 = V02*T10 + V12*T11 + V22*T12;
    const float a = T00*v0 + T01*v1 + T02*v2 + 0.3f;
    const float b = T00*w0 + T01*w1 + T02*w2;
    const float c = T10*w0 + T11*w1 + T12*w2 + 0.3f;

    const float det = a*c - b*b;
    const bool valid = (depth > 0.2f) && (det > 0.0f);
    const float det_s = valid ? det : 1.0f;
    const float invd = 1.0f / det_s;
    const float ca = c * invd;
    const float cb = -b * invd;
    const float cc = a * invd;

    const float mid = 0.5f * (a + c);
    const float lam = mid + sqrtf(fmaxf(mid*mid - det, 0.1f));
    const float radius = valid ? ceilf(3.0f * sqrtf(lam)) : 0.0f;
    areas[2*n+0] = radius;
    areas[2*n+1] = radius;

    // view direction (twc = -Rcw^T tcw)
    const float twcx = -(R00*t0 + R10*t1 + R20*t2);
    const float twcy = -(R01*t0 + R11*t1 + R21*t2);
    const float twcz = -(R02*t0 + R12*t1 + R22*t2);
    float dxn = pwx - twcx, dyn = pwy - twcy, dzn = pwz - twcz;
    const float dinv = 1.0f / sqrtf(dxn*dxn + dyn*dyn + dzn*dzn);
    const float X = dxn*dinv, Y = dyn*dinv, Z = dzn*dinv;
    const float XX = X*X, YY = Y*Y, ZZ = Z*Z, XY = X*Y, YZ = Y*Z, XZ = X*Z;

    const float* sh = shs + n*48;
    float col[3];
#pragma unroll
    for (int ch = 0; ch < 3; ch++) {
        float res =  0.28209479177387814f * sh[0*3+ch];
        res += -0.4886025119029199f  * Y * sh[1*3+ch];
        res +=  0.4886025119029199f  * Z * sh[2*3+ch];
        res += -0.4886025119029199f  * X * sh[3*3+ch];
        res +=  1.0925484305920792f  * XY * sh[4*3+ch];
        res += -1.0925484305920792f  * YZ * sh[5*3+ch];
        res +=  0.31539156525252005f * (2.0f*ZZ - XX - YY) * sh[6*3+ch];
        res += -1.0925484305920792f  * XZ * sh[7*3+ch];
        res +=  0.5462742152960396f  * (XX - YY) * sh[8*3+ch];
        res += -0.5900435899266435f  * Y * (3.0f*XX - YY) * sh[9*3+ch];
        res +=  2.890611442640554f   * XY * Z * sh[10*3+ch];
        res += -0.4570457994644658f  * Y * (4.0f*ZZ - XX - YY) * sh[11*3+ch];
        res +=  0.3731763325901154f  * Z * (2.0f*ZZ - 3.0f*XX - 3.0f*YY) * sh[12*3+ch];
        res += -0.4570457994644658f  * X * (4.0f*ZZ - XX - YY) * sh[13*3+ch];
        res +=  1.445305721320277f   * Z * (XX - YY) * sh[14*3+ch];
        res += -0.5900435899266435f  * X * (XX - 3.0f*YY) * sh[15*3+ch];
        col[ch] = fmaxf(res + 0.5f, 0.0f);
    }

    // conservative support half-extents: alp >= 1/255 requires Q <= ln(255*alpha)
    const float tthr = logf(255.0f * alpha);
    float ex, ey;
    if (valid && tthr > 0.0f) {
        ex = sqrtf(2.0f * tthr * a) + 1.0f;   // +1px safety margin
        ey = sqrtf(2.0f * tthr * c) + 1.0f;
    } else {
        ex = -1e30f; ey = -1e30f;             // never overlaps any tile
    }

    g_pre[n*3+0] = make_float4(ux, uy, ca, cb);
    g_pre[n*3+1] = make_float4(cc, alpha, ex, ey);
    g_pre[n*3+2] = make_float4(col[0], col[1], col[2], 0.0f);

    // sortable key: float -> monotone uint, packed with index for a unique stable key
    unsigned ub = __float_as_uint(depth);
    ub = (ub & 0x80000000u) ? ~ub : (ub | 0x80000000u);
    g_bufA[n] = ((unsigned long long)ub << 16) | (unsigned)n;
}

// ---------------- 2. depth argsort: single-CTA 4x8-bit LSD radix, stable ----------------
// (config-A version: shared atomicAdd histograms — measured fastest variant)
__global__ void __launch_bounds__(1024) sort_kernel()
{
    __shared__ unsigned hist[32][256];   // per-warp digit counts -> running scatter offsets
    __shared__ unsigned dbase[256];      // digit totals -> exclusive digit bases

    const int tid  = threadIdx.x;
    const int wid  = tid >> 5;
    const int lane = tid & 31;
    const unsigned FULL = 0xffffffffu;

    unsigned long long* src = g_bufA;
    unsigned long long* dst = g_bufB;

#pragma unroll
    for (int pass = 0; pass < 4; pass++) {
        const int shift = 16 + 8 * pass;

        // zero per-warp histograms
        for (int i = tid; i < 32 * 256; i += 1024)
            ((unsigned*)hist)[i] = 0u;
        __syncthreads();

        // load 8 elements per thread; element order = (wid, slot, lane) ascending
        unsigned long long v[8];
        int d[8];
#pragma unroll
        for (int s = 0; s < 8; s++) {
            v[s] = src[wid * 256 + s * 32 + lane];
            d[s] = (int)((v[s] >> shift) & 255u);
        }
        // per-warp histogram (private row: no cross-warp contention; spread ATOMS ~LSU floor)
#pragma unroll
        for (int s = 0; s < 8; s++)
            atomicAdd(&hist[wid][d[s]], 1u);
        __syncthreads();

        // digit totals
        if (tid < 256) {
            unsigned tot = 0;
#pragma unroll
            for (int w = 0; w < 32; w++) tot += hist[w][tid];
            dbase[tid] = tot;
        }
        __syncthreads();

        // exclusive scan of 256 digit totals (warp 0, 8 values per lane)
        if (tid < 32) {
            unsigned x[8], e[8], s = 0;
#pragma unroll
            for (int k = 0; k < 8; k++) { x[k] = dbase[tid * 8 + k]; e[k] = s; s += x[k]; }
            unsigned inc = s;
#pragma unroll
            for (int off = 1; off < 32; off <<= 1) {
                unsigned nval = __shfl_up_sync(FULL, inc, off);
                if (lane >= off) inc += nval;
            }
            const unsigned wexcl = inc - s;
#pragma unroll
            for (int k = 0; k < 8; k++) dbase[tid * 8 + k] = wexcl + e[k];
        }
        __syncthreads();

        // convert per-warp counts into absolute running start offsets (warp-major stable)
        if (tid < 256) {
            unsigned running = dbase[tid];
#pragma unroll
            for (int w = 0; w < 32; w++) {
                unsigned tmp = hist[w][tid];
                hist[w][tid] = running;
                running += tmp;
            }
        }
        __syncthreads();

        // stable scatter, slot by slot (slot order preserves intra-thread order)
#pragma unroll
        for (int s = 0; s < 8; s++) {
            const unsigned peers  = __match_any_sync(FULL, d[s]);
            const unsigned rank   = __popc(peers & ((1u << lane) - 1u));
            const int      leader = __ffs(peers) - 1;
            unsigned base_o = 0;
            if (lane == leader) base_o = hist[wid][d[s]];
            base_o = __shfl_sync(FULL, base_o, leader);
            dst[base_o + rank] = v[s];
            if (lane == leader) hist[wid][d[s]] = base_o + __popc(peers);
        }
        __syncthreads();   // dst (global) visible to block before next pass reads it

        unsigned long long* t = src; src = dst; dst = t;
    }
    // 4 passes: A->B->A->B->A : final sorted sequence lives in g_bufA
}

// ---------------- 3. gather into sorted order ----------------
__global__ void gather_kernel()
{
    const int s = blockIdx.x * blockDim.x + threadIdx.x;
    if (s < NG) {
        const int g = (int)(g_bufA[s] & 0xFFFFu);
        const float4 p0 = g_pre[g*3+0];
        const float4 p1 = g_pre[g*3+1];
        g_pack[s*3+0] = p0;
        g_pack[s*3+1] = p1;
        g_pack[s*3+2] = g_pre[g*3+2];
        g_cull[s] = make_float4(p0.x, p0.y, p1.z, p1.w);   // (ux, uy, ex, ey)
    }
}

// ---------------- 4. tile binning: smem-staged, 8 warps per CTA = 8 tiles --------------
// One coalesced 256-wide chunk load into smem serves all 8 warps; ballot rounds run
// against LDS (29 cyc) instead of serially-dependent L2 loads (round-13's 102us bug:
// MLP=1 LDG->ballot chain at ~400 cyc/iter).
__global__ void __launch_bounds__(256) binning_kernel()
{
    __shared__ float4 scv[256];
    const int tid  = threadIdx.x;
    const int wid  = tid >> 5;
    const int lane = tid & 31;
    const int t = blockIdx.x * 8 + wid;            // 32 CTAs x 8 warps = 256 tiles
    const float tx0 = (float)((t & 15) * 16), tx1 = tx0 + 15.0f;
    const float ty0 = (float)((t >> 4) * 16), ty1 = ty0 + 15.0f;

    unsigned short* lst = g_list + t * NG;
    int cnt = 0;
    for (int base = 0; base < NG; base += 256) {
        __syncthreads();                           // protect scv reuse across chunks
        scv[tid] = g_cull[base + tid];             // coalesced, latency hidden across warps
        __syncthreads();
#pragma unroll
        for (int j = 0; j < 8; j++) {
            const float4 cv = scv[j * 32 + lane];
            const bool keep = (cv.x - cv.z <= tx1) && (cv.x + cv.z >= tx0) &&
                              (cv.y - cv.w <= ty1) && (cv.y + cv.w >= ty0);
            const unsigned m = __ballot_sync(0xffffffffu, keep);
            if (keep)
                lst[cnt + __popc(m & ((1u << lane) - 1u))] =
                    (unsigned short)(base + j * 32 + lane);
            cnt += __popc(m);
        }
    }
    if (lane == 0) g_cnt[t] = cnt;
}

// ---------------- 5. tiled compositing over per-tile lists ----------------
__global__ void __launch_bounds__(256) render_kernel(float* __restrict__ out)
{
    __shared__ float4 s0[256];
    __shared__ float4 s1[256];
    __shared__ float  s2[256];

    const int tid = threadIdx.x;
    const int t = blockIdx.x;                       // tile id
    const int x = (t & 15) * 16 + (tid & 15);
    const int y = (t >> 4) * 16 + (tid >> 4);
    const float px = (float)x, py = (float)y;

    const unsigned short* lst = g_list + t * NG;
    const int nlist = g_cnt[t];

    float T = 1.0f, ar = 0.0f, ag = 0.0f, ab = 0.0f;
    int done = 0;

    for (int base = 0; base < nlist; base += 256) {
        const int n = min(256, nlist - base);
        if (tid < n) {
            const int idx = (int)lst[base + tid];
            const float4 p0 = g_pack[idx*3+0];      // (ux, uy, ca, cb)
            const float4 p1 = g_pack[idx*3+1];      // (cc, alpha, ex, ey)
            const float4 p2 = g_pack[idx*3+2];      // (r, g, b, 0)
            s0[tid] = p0;
            s1[tid] = make_float4(p1.x, p1.y, p2.x, p2.y);   // (cc, alpha, r, g)
            s2[tid] = p2.z;                                  // b
        }
        __syncthreads();                            // compaction visible before reads

        if (!done) {
            for (int i = 0; i < n; i++) {
                const float4 q0 = s0[i];
                const float4 q1 = s1[i];
                const float dx = px - q0.x;
                const float dy = py - q0.y;
                const float pw = -0.5f*(q0.z*dx*dx + q1.x*dy*dy) - q0.w*dx*dy;
                if (pw > 0.0f) continue;
                const float alp = fminf(0.99f, q1.y * __expf(pw));
                if (alp < (1.0f/255.0f)) continue;
                const float wgt = alp * T;
                ar += wgt * q1.z;
                ag += wgt * q1.w;
                ab += wgt * s2[i];
                T *= (1.0f - alp);
                if (T <= 1e-4f) { done = 1; break; }
            }
        }
        // consensus early-exit; also orders this chunk's reads before next chunk's writes
        if (__syncthreads_and(done)) break;
    }

    const int p = y * WW + x;
    out[p]         = ar;
    out[HWP + p]   = ag;
    out[2*HWP + p] = ab;
}

// ---------------- launch ----------------
extern "C" void kernel_launch(void* const* d_in, const int* in_sizes, int n_in,
                              void* d_out, int out_size)
{
    const float* pws        = (const float*)d_in[0];
    const float* shs        = (const float*)d_in[1];
    const float* alphas_raw = (const float*)d_in[2];
    const float* scales_raw = (const float*)d_in[3];
    const float* rots_raw   = (const float*)d_in[4];
    // d_in[5] = us (forward no-op)
    const float* Rcw        = (const float*)d_in[6];
    const float* tcw        = (const float*)d_in[7];
    const float* intr       = (const float*)d_in[8];
    float* out = (float*)d_out;

    preprocess_kernel<<<(NG + 255) / 256, 256>>>(pws, shs, alphas_raw, scales_raw, rots_raw,
                                                 Rcw, tcw, intr, out + 3 * HWP);
    sort_kernel<<<1, 1024>>>();
    gather_kernel<<<(NG + 255) / 256, 256>>>();
    binning_kernel<<<32, 256>>>();
    render_kernel<<<256, 256>>>(out);
}

// round 15
// speedup vs baseline: 1.7270x; 1.1492x over previous
#include <cuda_runtime.h>

#define NG   8192
#define HH   256
#define WW   256
#define HWP  (HH*WW)
#define NSEG 8
#define SEGSZ (NG/NSEG)   // 1024

// ---------------- device scratch (no allocations allowed) ----------------
__device__ unsigned long long g_bufA[NG];   // (sortable_key32 << 16) | idx16
__device__ unsigned long long g_bufB[NG];
__device__ float4 g_pre [NG*3];             // unsorted packed gaussians
__device__ float4 g_pack[NG*3];             // depth-sorted packed gaussians
__device__ float4 g_cull[NG];               // sorted cull vectors (ux, uy, ex, ey)
__device__ unsigned short g_list[256*NG];   // per-tile lists, segmented: [t*NG + seg*SEGSZ + i]
__device__ int g_cnt[NSEG*256];             // per-(segment, tile) list lengths

// pack layout per gaussian (3 float4):
//  [0] = (ux, uy, cinv_a, cinv_b)
//  [1] = (cinv_c, alpha, ex, ey)     ex/ey = conservative bbox half-extents (px); -1e30 => culled
//  [2] = (colR, colG, colB, 0)

// ---------------- 1. per-gaussian preprocess ----------------
__global__ void preprocess_kernel(const float* __restrict__ pws,
                                  const float* __restrict__ shs,
                                  const float* __restrict__ alphas_raw,
                                  const float* __restrict__ scales_raw,
                                  const float* __restrict__ rots_raw,
                                  const float* __restrict__ Rcw,
                                  const float* __restrict__ tcw,
                                  const float* __restrict__ intr,
                                  float* __restrict__ areas)
{
    int n = blockIdx.x * blockDim.x + threadIdx.x;
    if (n >= NG) return;

    const float fx = intr[0], fy = intr[1], cx = intr[2], cy = intr[3];
    const float R00 = Rcw[0], R01 = Rcw[1], R02 = Rcw[2];
    const float R10 = Rcw[3], R11 = Rcw[4], R12 = Rcw[5];
    const float R20 = Rcw[6], R21 = Rcw[7], R22 = Rcw[8];
    const float t0 = tcw[0], t1 = tcw[1], t2 = tcw[2];

    // vectorized inputs (kernel is load-latency-bound: 48 scalar LDG -> 12 LDG.128)
    float shv[48];
    {
        const float4* sh4 = (const float4*)(shs + n * 48);
#pragma unroll
        for (int i = 0; i < 12; i++) {
            const float4 v = sh4[i];
            shv[i*4+0] = v.x; shv[i*4+1] = v.y; shv[i*4+2] = v.z; shv[i*4+3] = v.w;
        }
    }
    const float4 q4 = ((const float4*)rots_raw)[n];
    const float pwx = pws[3*n+0], pwy = pws[3*n+1], pwz = pws[3*n+2];

    // camera-space point
    const float pcx = R00*pwx + R01*pwy + R02*pwz + t0;
    const float pcy = R10*pwx + R11*pwy + R12*pwz + t1;
    const float pcz = R20*pwx + R21*pwy + R22*pwz + t2;
    const float depth = pcz;
    const float zs = (depth > 0.2f) ? depth : 1.0f;
    const float iz = 1.0f / zs;

    const float ux = fx * pcx * iz + cx;
    const float uy = fy * pcy * iz + cy;

    // activations (fast-math: rel err ~1e-6, well inside 1e-3 budget; matched round-C rel_err)
    const float alpha = 1.0f / (1.0f + __expf(-alphas_raw[n]));
    const float sx = __expf(scales_raw[3*n+0]);
    const float sy = __expf(scales_raw[3*n+1]);
    const float sz = __expf(scales_raw[3*n+2]);

    float qw = q4.x, qx = q4.y, qy = q4.z, qz = q4.w;
    {
        const float qi = rsqrtf(qw*qw + qx*qx + qy*qy + qz*qz);
        qw *= qi; qx *= qi; qy *= qi; qz *= qi;
    }
    // rotation matrix
    const float r00 = 1.0f - 2.0f*(qy*qy + qz*qz), r01 = 2.0f*(qx*qy - qw*qz), r02 = 2.0f*(qx*qz + qw*qy);
    const float r10 = 2.0f*(qx*qy + qw*qz), r11 = 1.0f - 2.0f*(qx*qx + qz*qz), r12 = 2.0f*(qy*qz - qw*qx);
    const float r20 = 2.0f*(qx*qz - qw*qy), r21 = 2.0f*(qy*qz + qw*qx), r22 = 1.0f - 2.0f*(qx*qx + qy*qy);

    // M = R * diag(scales); cov3d = M M^T (symmetric 6)
    const float m00 = r00*sx, m01 = r01*sy, m02 = r02*sz;
    const float m10 = r10*sx, m11 = r11*sy, m12 = r12*sz;
    const float m20 = r20*sx, m21 = r21*sy, m22 = r22*sz;
    const float V00 = m00*m00 + m01*m01 + m02*m02;
    const float V01 = m00*m10 + m01*m11 + m02*m12;
    const float V02 = m00*m20 + m01*m21 + m02*m22;
    const float V11 = m10*m10 + m11*m11 + m12*m12;
    const float V12 = m10*m20 + m11*m21 + m12*m22;
    const float V22 = m20*m20 + m21*m21 + m22*m22;

    // Jacobian and T = J @ Rcw
    const float tanfx = WW / (2.0f * fx);
    const float tanfy = HH / (2.0f * fy);
    const float xn = pcx * iz, yn = pcy * iz;
    const float txl = fminf(fmaxf(xn, -1.3f*tanfx), 1.3f*tanfx) * zs;
    const float tyl = fminf(fmaxf(yn, -1.3f*tanfy), 1.3f*tanfy) * zs;
    const float iz2 = iz * iz;
    const float J00 = fx * iz, J02 = -fx * txl * iz2;
    const float J11 = fy * iz, J12 = -fy * tyl * iz2;
    const float T00 = J00*R00 + J02*R20;
    const float T01 = J00*R01 + J02*R21;
    const float T02 = J00*R02 + J02*R22;
    const float T10 = J11*R10 + J12*R20;
    const float T11 = J11*R11 + J12*R21;
    const float T12 = J11*R12 + J12*R22;

    // cov2d = T V T^T + 0.3 I
    const float v0 = V00*T00 + V01*T01 + V02*T02;
    const float v1 = V01*T00 + V11*T01 + V12*T02;
    const float v2 = V02*T00 + V12*T01 + V22*T02;
    const float w0 = V00*T10 + V01*T11 + V02*T12;
    const float w1 = V01*T10 + V11*T11 + V12*T12;
    const float w2 = V02*T10 + V12*T11 + V22*T12;
    const float a = T00*v0 + T01*v1 + T02*v2 + 0.3f;
    const float b = T00*w0 + T01*w1 + T02*w2;
    const float c = T10*w0 + T11*w1 + T12*w2 + 0.3f;

    const float det = a*c - b*b;
    const bool valid = (depth > 0.2f) && (det > 0.0f);
    const float det_s = valid ? det : 1.0f;
    const float invd = 1.0f / det_s;
    const float ca = c * invd;
    const float cb = -b * invd;
    const float cc = a * invd;

    const float mid = 0.5f * (a + c);
    const float lam = mid + sqrtf(fmaxf(mid*mid - det, 0.1f));
    const float radius = valid ? ceilf(3.0f * sqrtf(lam)) : 0.0f;
    areas[2*n+0] = radius;
    areas[2*n+1] = radius;

    // view direction (twc = -Rcw^T tcw)
    const float twcx = -(R00*t0 + R10*t1 + R20*t2);
    const float twcy = -(R01*t0 + R11*t1 + R21*t2);
    const float twcz = -(R02*t0 + R12*t1 + R22*t2);
    float dxn = pwx - twcx, dyn = pwy - twcy, dzn = pwz - twcz;
    const float dinv = rsqrtf(dxn*dxn + dyn*dyn + dzn*dzn);
    const float X = dxn*dinv, Y = dyn*dinv, Z = dzn*dinv;
    const float XX = X*X, YY = Y*Y, ZZ = Z*Z, XY = X*Y, YZ = Y*Z, XZ = X*Z;

    float col[3];
#pragma unroll
    for (int ch = 0; ch < 3; ch++) {
        float res =  0.28209479177387814f * shv[0*3+ch];
        res += -0.4886025119029199f  * Y * shv[1*3+ch];
        res +=  0.4886025119029199f  * Z * shv[2*3+ch];
        res += -0.4886025119029199f  * X * shv[3*3+ch];
        res +=  1.0925484305920792f  * XY * shv[4*3+ch];
        res += -1.0925484305920792f  * YZ * shv[5*3+ch];
        res +=  0.31539156525252005f * (2.0f*ZZ - XX - YY) * shv[6*3+ch];
        res += -1.0925484305920792f  * XZ * shv[7*3+ch];
        res +=  0.5462742152960396f  * (XX - YY) * shv[8*3+ch];
        res += -0.5900435899266435f  * Y * (3.0f*XX - YY) * shv[9*3+ch];
        res +=  2.890611442640554f   * XY * Z * shv[10*3+ch];
        res += -0.4570457994644658f  * Y * (4.0f*ZZ - XX - YY) * shv[11*3+ch];
        res +=  0.3731763325901154f  * Z * (2.0f*ZZ - 3.0f*XX - 3.0f*YY) * shv[12*3+ch];
        res += -0.4570457994644658f  * X * (4.0f*ZZ - XX - YY) * shv[13*3+ch];
        res +=  1.445305721320277f   * Z * (XX - YY) * shv[14*3+ch];
        res += -0.5900435899266435f  * X * (XX - 3.0f*YY) * shv[15*3+ch];
        col[ch] = fmaxf(res + 0.5f, 0.0f);
    }

    // conservative support half-extents: alp >= 1/255 requires Q <= ln(255*alpha)
    const float tthr = __logf(255.0f * alpha);
    float ex, ey;
    if (valid && tthr > 0.0f) {
        ex = sqrtf(2.0f * tthr * a) + 1.0f;   // +1px safety margin
        ey = sqrtf(2.0f * tthr * c) + 1.0f;
    } else {
        ex = -1e30f; ey = -1e30f;             // never overlaps any tile
    }

    g_pre[n*3+0] = make_float4(ux, uy, ca, cb);
    g_pre[n*3+1] = make_float4(cc, alpha, ex, ey);
    g_pre[n*3+2] = make_float4(col[0], col[1], col[2], 0.0f);

    // sortable key: float -> monotone uint, packed with index for a unique stable key
    unsigned ub = __float_as_uint(depth);
    ub = (ub & 0x80000000u) ? ~ub : (ub | 0x80000000u);
    g_bufA[n] = ((unsigned long long)ub << 16) | (unsigned)n;
}

// ---------------- 2. depth argsort: single-CTA 4x8-bit LSD radix, stable ----------------
// (config-A version: shared atomicAdd histograms — measured fastest variant)
__global__ void __launch_bounds__(1024) sort_kernel()
{
    __shared__ unsigned hist[32][256];   // per-warp digit counts -> running scatter offsets
    __shared__ unsigned dbase[256];      // digit totals -> exclusive digit bases

    const int tid  = threadIdx.x;
    const int wid  = tid >> 5;
    const int lane = tid & 31;
    const unsigned FULL = 0xffffffffu;

    unsigned long long* src = g_bufA;
    unsigned long long* dst = g_bufB;

#pragma unroll
    for (int pass = 0; pass < 4; pass++) {
        const int shift = 16 + 8 * pass;

        // zero per-warp histograms
        for (int i = tid; i < 32 * 256; i += 1024)
            ((unsigned*)hist)[i] = 0u;
        __syncthreads();

        // load 8 elements per thread; element order = (wid, slot, lane) ascending
        unsigned long long v[8];
        int d[8];
#pragma unroll
        for (int s = 0; s < 8; s++) {
            v[s] = src[wid * 256 + s * 32 + lane];
            d[s] = (int)((v[s] >> shift) & 255u);
        }
        // per-warp histogram (private row: no cross-warp contention)
#pragma unroll
        for (int s = 0; s < 8; s++)
            atomicAdd(&hist[wid][d[s]], 1u);
        __syncthreads();

        // digit totals
        if (tid < 256) {
            unsigned tot = 0;
#pragma unroll
            for (int w = 0; w < 32; w++) tot += hist[w][tid];
            dbase[tid] = tot;
        }
        __syncthreads();

        // exclusive scan of 256 digit totals (warp 0, 8 values per lane)
        if (tid < 32) {
            unsigned x[8], e[8], s = 0;
#pragma unroll
            for (int k = 0; k < 8; k++) { x[k] = dbase[tid * 8 + k]; e[k] = s; s += x[k]; }
            unsigned inc = s;
#pragma unroll
            for (int off = 1; off < 32; off <<= 1) {
                unsigned nval = __shfl_up_sync(FULL, inc, off);
                if (lane >= off) inc += nval;
            }
            const unsigned wexcl = inc - s;
#pragma unroll
            for (int k = 0; k < 8; k++) dbase[tid * 8 + k] = wexcl + e[k];
        }
        __syncthreads();

        // convert per-warp counts into absolute running start offsets (warp-major stable)
        if (tid < 256) {
            unsigned running = dbase[tid];
#pragma unroll
            for (int w = 0; w < 32; w++) {
                unsigned tmp = hist[w][tid];
                hist[w][tid] = running;
                running += tmp;
            }
        }
        __syncthreads();

        // stable scatter, slot by slot (slot order preserves intra-thread order)
#pragma unroll
        for (int s = 0; s < 8; s++) {
            const unsigned peers  = __match_any_sync(FULL, d[s]);
            const unsigned rank   = __popc(peers & ((1u << lane) - 1u));
            const int      leader = __ffs(peers) - 1;
            unsigned base_o = 0;
            if (lane == leader) base_o = hist[wid][d[s]];
            base_o = __shfl_sync(FULL, base_o, leader);
            dst[base_o + rank] = v[s];
            if (lane == leader) hist[wid][d[s]] = base_o + __popc(peers);
        }
        __syncthreads();   // dst (global) visible to block before next pass reads it

        unsigned long long* t = src; src = dst; dst = t;
    }
    // 4 passes: A->B->A->B->A : final sorted sequence lives in g_bufA
}

// ---------------- 3. gather into sorted order ----------------
__global__ void gather_kernel()
{
    const int s = blockIdx.x * blockDim.x + threadIdx.x;
    if (s < NG) {
        const int g = (int)(g_bufA[s] & 0xFFFFu);
        const float4 p0 = g_pre[g*3+0];
        const float4 p1 = g_pre[g*3+1];
        g_pack[s*3+0] = p0;
        g_pack[s*3+1] = p1;
        g_pack[s*3+2] = g_pre[g*3+2];
        g_cull[s] = make_float4(p0.x, p0.y, p1.z, p1.w);   // (ux, uy, ex, ey)
    }
}

// ---------------- 4. segmented tile binning: grid (32 tile-groups, 8 segments) --------
// Each CTA: 8 warps = 8 tiles, scans one 1024-gaussian segment of the sorted order via
// smem staging. Segments concatenated in order reproduce the full depth-sorted list,
// with 8x fewer serial ballot rounds per warp and full-chip occupancy.
__global__ void __launch_bounds__(256) binning_kernel()
{
    __shared__ float4 scv[256];
    const int tid  = threadIdx.x;
    const int wid  = tid >> 5;
    const int lane = tid & 31;
    const int t    = blockIdx.x * 8 + wid;         // tile id (0..255)
    const int seg  = blockIdx.y;                   // segment id (0..7)
    const float tx0 = (float)((t & 15) * 16), tx1 = tx0 + 15.0f;
    const float ty0 = (float)((t >> 4) * 16), ty1 = ty0 + 15.0f;

    unsigned short* lst = g_list + t * NG + seg * SEGSZ;
    int cnt = 0;
    for (int base = seg * SEGSZ; base < (seg + 1) * SEGSZ; base += 256) {
        __syncthreads();                           // protect scv reuse across chunks
        scv[tid] = g_cull[base + tid];             // coalesced, latency hidden across warps
        __syncthreads();
#pragma unroll
        for (int j = 0; j < 8; j++) {
            const float4 cv = scv[j * 32 + lane];
            const bool keep = (cv.x - cv.z <= tx1) && (cv.x + cv.z >= tx0) &&
                              (cv.y - cv.w <= ty1) && (cv.y + cv.w >= ty0);
            const unsigned m = __ballot_sync(0xffffffffu, keep);
            if (keep)
                lst[cnt + __popc(m & ((1u << lane) - 1u))] =
                    (unsigned short)(base + j * 32 + lane);
            cnt += __popc(m);
        }
    }
    if (lane == 0) g_cnt[seg * 256 + t] = cnt;
}

// ---------------- 5. tiled compositing over per-tile segmented lists -------------------
__global__ void __launch_bounds__(256) render_kernel(float* __restrict__ out)
{
    __shared__ float4 s0[256];
    __shared__ float4 s1[256];
    __shared__ float  s2[256];

    const int tid = threadIdx.x;
    const int t = blockIdx.x;                       // tile id
    const int x = (t & 15) * 16 + (tid & 15);
    const int y = (t >> 4) * 16 + (tid >> 4);
    const float px = (float)x, py = (float)y;

    const unsigned short* lstT = g_list + t * NG;

    float T = 1.0f, ar = 0.0f, ag = 0.0f, ab = 0.0f;
    int done = 0;

    for (int seg = 0; seg < NSEG; seg++) {
        const int scnt = g_cnt[seg * 256 + t];      // uniform across block
        for (int base = 0; base < scnt; base += 256) {
            const int n = min(256, scnt - base);
            if (tid < n) {
                const int idx = (int)lstT[seg * SEGSZ + base + tid];
                const float4 p0 = g_pack[idx*3+0];  // (ux, uy, ca, cb)
                const float4 p1 = g_pack[idx*3+1];  // (cc, alpha, ex, ey)
                const float4 p2 = g_pack[idx*3+2];  // (r, g, b, 0)
                s0[tid] = p0;
                s1[tid] = make_float4(p1.x, p1.y, p2.x, p2.y);   // (cc, alpha, r, g)
                s2[tid] = p2.z;                                  // b
            }
            __syncthreads();                        // compaction visible before reads

            if (!done) {
                for (int i = 0; i < n; i++) {
                    const float4 q0 = s0[i];
                    const float4 q1 = s1[i];
                    const float dx = px - q0.x;
                    const float dy = py - q0.y;
                    const float pw = -0.5f*(q0.z*dx*dx + q1.x*dy*dy) - q0.w*dx*dy;
                    if (pw > 0.0f) continue;
                    const float alp = fminf(0.99f, q1.y * __expf(pw));
                    if (alp < (1.0f/255.0f)) continue;
                    const float wgt = alp * T;
                    ar += wgt * q1.z;
                    ag += wgt * q1.w;
                    ab += wgt * s2[i];
                    T *= (1.0f - alp);
                    if (T <= 1e-4f) { done = 1; break; }
                }
            }
            // consensus early-exit; also orders this chunk's reads before next chunk's writes
            if (__syncthreads_and(done)) goto finished;
        }
    }
finished:
    ;
    const int p = y * WW + x;
    out[p]         = ar;
    out[HWP + p]   = ag;
    out[2*HWP + p] = ab;
}

// ---------------- launch ----------------
extern "C" void kernel_launch(void* const* d_in, const int* in_sizes, int n_in,
                              void* d_out, int out_size)
{
    const float* pws        = (const float*)d_in[0];
    const float* shs        = (const float*)d_in[1];
    const float* alphas_raw = (const float*)d_in[2];
    const float* scales_raw = (const float*)d_in[3];
    const float* rots_raw   = (const float*)d_in[4];
    // d_in[5] = us (forward no-op)
    const float* Rcw        = (const float*)d_in[6];
    const float* tcw        = (const float*)d_in[7];
    const float* intr       = (const float*)d_in[8];
    float* out = (float*)d_out;

    preprocess_kernel<<<(NG + 255) / 256, 256>>>(pws, shs, alphas_raw, scales_raw, rots_raw,
                                                 Rcw, tcw, intr, out + 3 * HWP);
    sort_kernel<<<1, 1024>>>();
    gather_kernel<<<(NG + 255) / 256, 256>>>();
    binning_kernel<<<dim3(32, NSEG), 256>>>();
    render_kernel<<<256, 256>>>(out);
}

// round 16
// speedup vs baseline: 1.9710x; 1.1413x over previous
#include <cuda_runtime.h>

#define NG   8192
#define HH   256
#define WW   256
#define HWP  (HH*WW)
#define NSEG 8
#define SEGSZ (NG/NSEG)   // 1024

// ---------------- device scratch (no allocations allowed) ----------------
__device__ unsigned long long g_bufA[NG];   // (sortable_key32 << 16) | idx16 (preprocess out)
__device__ int    g_order[NG];              // sorted original indices (sort out)
__device__ float4 g_pre [NG*3];             // unsorted packed gaussians
__device__ float4 g_pack[NG*3];             // depth-sorted packed gaussians
__device__ float4 g_cull[NG];               // sorted cull vectors (ux, uy, ex, ey)
__device__ unsigned short g_list[256*NG];   // per-tile lists, segmented: [t*NG + seg*SEGSZ + i]
__device__ int g_cnt[NSEG*256];             // per-(segment, tile) list lengths

// pack layout per gaussian (3 float4):
//  [0] = (ux, uy, cinv_a, cinv_b)
//  [1] = (cinv_c, alpha, ex, ey)     ex/ey = conservative bbox half-extents (px); -1e30 => culled
//  [2] = (colR, colG, colB, 0)

// ---------------- 1. per-gaussian preprocess ----------------
__global__ void preprocess_kernel(const float* __restrict__ pws,
                                  const float* __restrict__ shs,
                                  const float* __restrict__ alphas_raw,
                                  const float* __restrict__ scales_raw,
                                  const float* __restrict__ rots_raw,
                                  const float* __restrict__ Rcw,
                                  const float* __restrict__ tcw,
                                  const float* __restrict__ intr,
                                  float* __restrict__ areas)
{
    int n = blockIdx.x * blockDim.x + threadIdx.x;
    if (n >= NG) return;

    const float fx = intr[0], fy = intr[1], cx = intr[2], cy = intr[3];
    const float R00 = Rcw[0], R01 = Rcw[1], R02 = Rcw[2];
    const float R10 = Rcw[3], R11 = Rcw[4], R12 = Rcw[5];
    const float R20 = Rcw[6], R21 = Rcw[7], R22 = Rcw[8];
    const float t0 = tcw[0], t1 = tcw[1], t2 = tcw[2];

    // vectorized inputs (kernel is load-latency-bound)
    float shv[48];
    {
        const float4* sh4 = (const float4*)(shs + n * 48);
#pragma unroll
        for (int i = 0; i < 12; i++) {
            const float4 v = sh4[i];
            shv[i*4+0] = v.x; shv[i*4+1] = v.y; shv[i*4+2] = v.z; shv[i*4+3] = v.w;
        }
    }
    const float4 q4 = ((const float4*)rots_raw)[n];
    const float pwx = pws[3*n+0], pwy = pws[3*n+1], pwz = pws[3*n+2];

    // camera-space point
    const float pcx = R00*pwx + R01*pwy + R02*pwz + t0;
    const float pcy = R10*pwx + R11*pwy + R12*pwz + t1;
    const float pcz = R20*pwx + R21*pwy + R22*pwz + t2;
    const float depth = pcz;
    const float zs = (depth > 0.2f) ? depth : 1.0f;
    const float iz = 1.0f / zs;

    const float ux = fx * pcx * iz + cx;
    const float uy = fy * pcy * iz + cy;

    // activations (fast-math: rel err ~1e-6, well inside 1e-3 budget)
    const float alpha = 1.0f / (1.0f + __expf(-alphas_raw[n]));
    const float sx = __expf(scales_raw[3*n+0]);
    const float sy = __expf(scales_raw[3*n+1]);
    const float sz = __expf(scales_raw[3*n+2]);

    float qw = q4.x, qx = q4.y, qy = q4.z, qz = q4.w;
    {
        const float qi = rsqrtf(qw*qw + qx*qx + qy*qy + qz*qz);
        qw *= qi; qx *= qi; qy *= qi; qz *= qi;
    }
    // rotation matrix
    const float r00 = 1.0f - 2.0f*(qy*qy + qz*qz), r01 = 2.0f*(qx*qy - qw*qz), r02 = 2.0f*(qx*qz + qw*qy);
    const float r10 = 2.0f*(qx*qy + qw*qz), r11 = 1.0f - 2.0f*(qx*qx + qz*qz), r12 = 2.0f*(qy*qz - qw*qx);
    const float r20 = 2.0f*(qx*qz - qw*qy), r21 = 2.0f*(qy*qz + qw*qx), r22 = 1.0f - 2.0f*(qx*qx + qy*qy);

    // M = R * diag(scales); cov3d = M M^T (symmetric 6)
    const float m00 = r00*sx, m01 = r01*sy, m02 = r02*sz;
    const float m10 = r10*sx, m11 = r11*sy, m12 = r12*sz;
    const float m20 = r20*sx, m21 = r21*sy, m22 = r22*sz;
    const float V00 = m00*m00 + m01*m01 + m02*m02;
    const float V01 = m00*m10 + m01*m11 + m02*m12;
    const float V02 = m00*m20 + m01*m21 + m02*m22;
    const float V11 = m10*m10 + m11*m11 + m12*m12;
    const float V12 = m10*m20 + m11*m21 + m12*m22;
    const float V22 = m20*m20 + m21*m21 + m22*m22;

    // Jacobian and T = J @ Rcw
    const float tanfx = WW / (2.0f * fx);
    const float tanfy = HH / (2.0f * fy);
    const float xn = pcx * iz, yn = pcy * iz;
    const float txl = fminf(fmaxf(xn, -1.3f*tanfx), 1.3f*tanfx) * zs;
    const float tyl = fminf(fmaxf(yn, -1.3f*tanfy), 1.3f*tanfy) * zs;
    const float iz2 = iz * iz;
    const float J00 = fx * iz, J02 = -fx * txl * iz2;
    const float J11 = fy * iz, J12 = -fy * tyl * iz2;
    const float T00 = J00*R00 + J02*R20;
    const float T01 = J00*R01 + J02*R21;
    const float T02 = J00*R02 + J02*R22;
    const float T10 = J11*R10 + J12*R20;
    const float T11 = J11*R11 + J12*R21;
    const float T12 = J11*R12 + J12*R22;

    // cov2d = T V T^T + 0.3 I
    const float v0 = V00*T00 + V01*T01 + V02*T02;
    const float v1 = V01*T00 + V11*T01 + V12*T02;
    const float v2 = V02*T00 + V12*T01 + V22*T02;
    const float w0 = V00*T10 + V01*T11 + V02*T12;
    const float w1 = V01*T10 + V11*T11 + V12*T12;
    const float w2 = V02*T10 + V12*T11 + V22*T12;
    const float a = T00*v0 + T01*v1 + T02*v2 + 0.3f;
    const float b = T00*w0 + T01*w1 + T02*w2;
    const float c = T10*w0 + T11*w1 + T12*w2 + 0.3f;

    const float det = a*c - b*b;
    const bool valid = (depth > 0.2f) && (det > 0.0f);
    const float det_s = valid ? det : 1.0f;
    const float invd = 1.0f / det_s;
    const float ca = c * invd;
    const float cb = -b * invd;
    const float cc = a * invd;

    const float mid = 0.5f * (a + c);
    const float lam = mid + sqrtf(fmaxf(mid*mid - det, 0.1f));
    const float radius = valid ? ceilf(3.0f * sqrtf(lam)) : 0.0f;
    areas[2*n+0] = radius;
    areas[2*n+1] = radius;

    // view direction (twc = -Rcw^T tcw)
    const float twcx = -(R00*t0 + R10*t1 + R20*t2);
    const float twcy = -(R01*t0 + R11*t1 + R21*t2);
    const float twcz = -(R02*t0 + R12*t1 + R22*t2);
    float dxn = pwx - twcx, dyn = pwy - twcy, dzn = pwz - twcz;
    const float dinv = rsqrtf(dxn*dxn + dyn*dyn + dzn*dzn);
    const float X = dxn*dinv, Y = dyn*dinv, Z = dzn*dinv;
    const float XX = X*X, YY = Y*Y, ZZ = Z*Z, XY = X*Y, YZ = Y*Z, XZ = X*Z;

    float col[3];
#pragma unroll
    for (int ch = 0; ch < 3; ch++) {
        float res =  0.28209479177387814f * shv[0*3+ch];
        res += -0.4886025119029199f  * Y * shv[1*3+ch];
        res +=  0.4886025119029199f  * Z * shv[2*3+ch];
        res += -0.4886025119029199f  * X * shv[3*3+ch];
        res +=  1.0925484305920792f  * XY * shv[4*3+ch];
        res += -1.0925484305920792f  * YZ * shv[5*3+ch];
        res +=  0.31539156525252005f * (2.0f*ZZ - XX - YY) * shv[6*3+ch];
        res += -1.0925484305920792f  * XZ * shv[7*3+ch];
        res +=  0.5462742152960396f  * (XX - YY) * shv[8*3+ch];
        res += -0.5900435899266435f  * Y * (3.0f*XX - YY) * shv[9*3+ch];
        res +=  2.890611442640554f   * XY * Z * shv[10*3+ch];
        res += -0.4570457994644658f  * Y * (4.0f*ZZ - XX - YY) * shv[11*3+ch];
        res +=  0.3731763325901154f  * Z * (2.0f*ZZ - 3.0f*XX - 3.0f*YY) * shv[12*3+ch];
        res += -0.4570457994644658f  * X * (4.0f*ZZ - XX - YY) * shv[13*3+ch];
        res +=  1.445305721320277f   * Z * (XX - YY) * shv[14*3+ch];
        res += -0.5900435899266435f  * X * (XX - 3.0f*YY) * shv[15*3+ch];
        col[ch] = fmaxf(res + 0.5f, 0.0f);
    }

    // conservative support half-extents: alp >= 1/255 requires Q <= ln(255*alpha)
    const float tthr = __logf(255.0f * alpha);
    float ex, ey;
    if (valid && tthr > 0.0f) {
        ex = sqrtf(2.0f * tthr * a) + 1.0f;   // +1px safety margin
        ey = sqrtf(2.0f * tthr * c) + 1.0f;
    } else {
        ex = -1e30f; ey = -1e30f;             // never overlaps any tile
    }

    g_pre[n*3+0] = make_float4(ux, uy, ca, cb);
    g_pre[n*3+1] = make_float4(cc, alpha, ex, ey);
    g_pre[n*3+2] = make_float4(col[0], col[1], col[2], 0.0f);

    // sortable key: float -> monotone uint, packed with index for a unique stable key
    unsigned ub = __float_as_uint(depth);
    ub = (ub & 0x80000000u) ? ~ub : (ub | 0x80000000u);
    g_bufA[n] = ((unsigned long long)ub << 16) | (unsigned)n;
}

// ---------------- 2. depth argsort: single-CTA 4x8-bit LSD radix, fully in-smem --------
// 1024 threads = 32 warps, 8 elements/thread. Key = bits [16,48) of the packed u64.
// The whole 48-bit-key array stays resident in 48KB shared between passes (split
// u32 low + u16 high), ALIASED over the 32KB histogram region. Phase discipline:
// v[8] lives in registers during hist/rank phases; scatter positions are computed
// into registers before the staging writes clobber hist; dbase lives in the u16
// region and is dead before staging writes. Scattered global STG.64 (the old
// per-pass cost driver, ~8K L1tex wavefronts) becomes scattered STS.
__global__ void __launch_bounds__(1024) sort_kernel()
{
    __shared__ __align__(16) unsigned char sbuf[49152];     // 48KB union
    unsigned*       hist  = (unsigned*)sbuf;                // [32][256]  (hist phase)
    unsigned*       dbase = (unsigned*)(sbuf + 32768);      // [256]      (hist phase)
    unsigned*       keyA  = (unsigned*)sbuf;                // [8192] low 32 (staging phase)
    unsigned short* keyB  = (unsigned short*)(sbuf + 32768);// [8192] high 16 (staging phase)

    const int tid  = threadIdx.x;
    const int wid  = tid >> 5;
    const int lane = tid & 31;
    const unsigned FULL = 0xffffffffu;

#pragma unroll
    for (int pass = 0; pass < 4; pass++) {
        const int shift = 16 + 8 * pass;

        // load 8 elements into registers (from global on pass 0, staging after)
        unsigned long long v[8];
        int d[8];
#pragma unroll
        for (int s = 0; s < 8; s++) {
            const int i = wid * 256 + s * 32 + lane;
            if (pass == 0) v[s] = g_bufA[i];
            else           v[s] = ((unsigned long long)keyB[i] << 32) | keyA[i];
            d[s] = (int)((v[s] >> shift) & 255u);
        }
        __syncthreads();              // staging fully read before hist zeroing clobbers it

        // zero per-warp histograms (first 32KB only)
        for (int i = tid; i < 32 * 256; i += 1024)
            hist[i] = 0u;
        __syncthreads();

        // per-warp histogram (private row: no cross-warp contention)
#pragma unroll
        for (int s = 0; s < 8; s++)
            atomicAdd(&hist[wid * 256 + d[s]], 1u);
        __syncthreads();

        // digit totals
        if (tid < 256) {
            unsigned tot = 0;
#pragma unroll
            for (int w = 0; w < 32; w++) tot += hist[w * 256 + tid];
            dbase[tid] = tot;
        }
        __syncthreads();

        // exclusive scan of 256 digit totals (warp 0, 8 values per lane)
        if (tid < 32) {
            unsigned x[8], e[8], s = 0;
#pragma unroll
            for (int k = 0; k < 8; k++) { x[k] = dbase[tid * 8 + k]; e[k] = s; s += x[k]; }
            unsigned inc = s;
#pragma unroll
            for (int off = 1; off < 32; off <<= 1) {
                unsigned nval = __shfl_up_sync(FULL, inc, off);
                if (lane >= off) inc += nval;
            }
            const unsigned wexcl = inc - s;
#pragma unroll
            for (int k = 0; k < 8; k++) dbase[tid * 8 + k] = wexcl + e[k];
        }
        __syncthreads();

        // convert per-warp counts into absolute running start offsets (warp-major stable)
        if (tid < 256) {
            unsigned running = dbase[tid];
#pragma unroll
            for (int w = 0; w < 32; w++) {
                unsigned tmp = hist[w * 256 + tid];
                hist[w * 256 + tid] = running;
                running += tmp;
            }
        }
        __syncthreads();

        // phase A: compute all scatter positions into registers (consumes hist)
        unsigned pos[8];
#pragma unroll
        for (int s = 0; s < 8; s++) {
            const unsigned peers  = __match_any_sync(FULL, d[s]);
            const unsigned rank   = __popc(peers & ((1u << lane) - 1u));
            const int      leader = __ffs(peers) - 1;
            unsigned base_o = 0;
            if (lane == leader) base_o = hist[wid * 256 + d[s]];
            base_o = __shfl_sync(FULL, base_o, leader);
            pos[s] = base_o + rank;
            if (lane == leader) hist[wid * 256 + d[s]] = base_o + __popc(peers);
        }
        __syncthreads();              // hist dead; staging writes may now clobber it

        // phase B: scatter into smem staging (keyA/keyB alias hist+dbase)
#pragma unroll
        for (int s = 0; s < 8; s++) {
            keyA[pos[s]] = (unsigned)v[s];
            keyB[pos[s]] = (unsigned short)(v[s] >> 32);
        }
        __syncthreads();
    }

    // sorted order: original index is low 16 bits of the packed key
    for (int i = tid; i < NG; i += 1024)
        g_order[i] = (int)(keyA[i] & 0xFFFFu);
}

// ---------------- 3. gather into sorted order ----------------
__global__ void gather_kernel()
{
    const int s = blockIdx.x * blockDim.x + threadIdx.x;
    if (s < NG) {
        const int g = g_order[s];
        const float4 p0 = g_pre[g*3+0];
        const float4 p1 = g_pre[g*3+1];
        g_pack[s*3+0] = p0;
        g_pack[s*3+1] = p1;
        g_pack[s*3+2] = g_pre[g*3+2];
        g_cull[s] = make_float4(p0.x, p0.y, p1.z, p1.w);   // (ux, uy, ex, ey)
    }
}

// ---------------- 4. segmented tile binning: grid (32 tile-groups, 8 segments) --------
__global__ void __launch_bounds__(256) binning_kernel()
{
    __shared__ float4 scv[256];
    const int tid  = threadIdx.x;
    const int wid  = tid >> 5;
    const int lane = tid & 31;
    const int t    = blockIdx.x * 8 + wid;         // tile id (0..255)
    const int seg  = blockIdx.y;                   // segment id (0..7)
    const float tx0 = (float)((t & 15) * 16), tx1 = tx0 + 15.0f;
    const float ty0 = (float)((t >> 4) * 16), ty1 = ty0 + 15.0f;

    unsigned short* lst = g_list + t * NG + seg * SEGSZ;
    int cnt = 0;
    for (int base = seg * SEGSZ; base < (seg + 1) * SEGSZ; base += 256) {
        __syncthreads();                           // protect scv reuse across chunks
        scv[tid] = g_cull[base + tid];             // coalesced, latency hidden across warps
        __syncthreads();
#pragma unroll
        for (int j = 0; j < 8; j++) {
            const float4 cv = scv[j * 32 + lane];
            const bool keep = (cv.x - cv.z <= tx1) && (cv.x + cv.z >= tx0) &&
                              (cv.y - cv.w <= ty1) && (cv.y + cv.w >= ty0);
            const unsigned m = __ballot_sync(0xffffffffu, keep);
            if (keep)
                lst[cnt + __popc(m & ((1u << lane) - 1u))] =
                    (unsigned short)(base + j * 32 + lane);
            cnt += __popc(m);
        }
    }
    if (lane == 0) g_cnt[seg * 256 + t] = cnt;
}

// ---------------- 5. tiled compositing, virtual-concatenated segment lists -------------
__global__ void __launch_bounds__(256) render_kernel(float* __restrict__ out)
{
    __shared__ float4 s0[256];
    __shared__ float4 s1[256];
    __shared__ float  s2[256];
    __shared__ int    pre[NSEG + 1];

    const int tid = threadIdx.x;
    const int t = blockIdx.x;                       // tile id
    const int x = (t & 15) * 16 + (tid & 15);
    const int y = (t >> 4) * 16 + (tid >> 4);
    const float px = (float)x, py = (float)y;

    const unsigned short* lstT = g_list + t * NG;

    // segment-count prefix (virtual concatenation of the 8 depth-ordered sublists)
    if (tid == 0) {
        int acc = 0;
        pre[0] = 0;
#pragma unroll
        for (int s = 0; s < NSEG; s++) { acc += g_cnt[s * 256 + t]; pre[s + 1] = acc; }
    }
    __syncthreads();
    const int nlist = pre[NSEG];

    float T = 1.0f, ar = 0.0f, ag = 0.0f, ab = 0.0f;
    int done = 0;

    for (int base = 0; base < nlist; base += 256) {
        const int n = min(256, nlist - base);
        if (tid < n) {
            const int i = base + tid;
            int seg = 0;
#pragma unroll
            for (int s = 0; s < NSEG - 1; s++) if (i >= pre[s + 1]) seg = s + 1;
            const int idx = (int)lstT[seg * SEGSZ + (i - pre[seg])];
            const float4 p0 = g_pack[idx*3+0];      // (ux, uy, ca, cb)
            const float4 p1 = g_pack[idx*3+1];      // (cc, alpha, ex, ey)
            const float4 p2 = g_pack[idx*3+2];      // (r, g, b, 0)
            s0[tid] = p0;
            s1[tid] = make_float4(p1.x, p1.y, p2.x, p2.y);   // (cc, alpha, r, g)
            s2[tid] = p2.z;                                  // b
        }
        __syncthreads();                            // compaction visible before reads

        if (!done) {
            for (int i = 0; i < n; i++) {
                const float4 q0 = s0[i];
                const float4 q1 = s1[i];
                const float dx = px - q0.x;
                const float dy = py - q0.y;
                const float pw = -0.5f*(q0.z*dx*dx + q1.x*dy*dy) - q0.w*dx*dy;
                if (pw > 0.0f) continue;
                const float alp = fminf(0.99f, q1.y * __expf(pw));
                if (alp < (1.0f/255.0f)) continue;
                const float wgt = alp * T;
                ar += wgt * q1.z;
                ag += wgt * q1.w;
                ab += wgt * s2[i];
                T *= (1.0f - alp);
                if (T <= 1e-4f) { done = 1; break; }
            }
        }
        // consensus early-exit; also orders this chunk's reads before next chunk's writes
        if (__syncthreads_and(done)) break;
    }

    const int p = y * WW + x;
    out[p]         = ar;
    out[HWP + p]   = ag;
    out[2*HWP + p] = ab;
}

// ---------------- launch ----------------
extern "C" void kernel_launch(void* const* d_in, const int* in_sizes, int n_in,
                              void* d_out, int out_size)
{
    const float* pws        = (const float*)d_in[0];
    const float* shs        = (const float*)d_in[1];
    const float* alphas_raw = (const float*)d_in[2];
    const float* scales_raw = (const float*)d_in[3];
    const float* rots_raw   = (const float*)d_in[4];
    // d_in[5] = us (forward no-op)
    const float* Rcw        = (const float*)d_in[6];
    const float* tcw        = (const float*)d_in[7];
    const float* intr       = (const float*)d_in[8];
    float* out = (float*)d_out;

    preprocess_kernel<<<(NG + 255) / 256, 256>>>(pws, shs, alphas_raw, scales_raw, rots_raw,
                                                 Rcw, tcw, intr, out + 3 * HWP);
    sort_kernel<<<1, 1024>>>();
    gather_kernel<<<(NG + 255) / 256, 256>>>();
    binning_kernel<<<dim3(32, NSEG), 256>>>();
    render_kernel<<<256, 256>>>(out);
}

// round 17
// speedup vs baseline: 2.1219x; 1.0765x over previous
#include <cuda_runtime.h>

#define NG   8192
#define HH   256
#define WW   256
#define HWP  (HH*WW)
#define NSEG 8
#define SEGSZ (NG/NSEG)   // 1024

// ---------------- device scratch (no allocations allowed) ----------------
__device__ unsigned long long g_bufA[NG];   // (sortable_key32 << 16) | idx16 (preprocess out)
__device__ int    g_order[NG];              // sorted original indices (sort out)
__device__ float4 g_pre [NG*3];             // unsorted packed gaussians
__device__ float4 g_pack[NG*3];             // depth-sorted packed gaussians
__device__ float4 g_cull[NG];               // sorted cull vectors (ux, uy, ex, ey)
__device__ unsigned short g_list[256*NG];   // per-tile lists, segmented: [t*NG + seg*SEGSZ + i]
__device__ int g_cnt[NSEG*256];             // per-(segment, tile) list lengths

// pack layout per gaussian (3 float4):
//  [0] = (ux, uy, cinv_a, cinv_b)
//  [1] = (cinv_c, alpha, ex, ey)     ex/ey = conservative bbox half-extents (px); -1e30 => culled
//  [2] = (colR, colG, colB, 0)

// ---------------- 1. per-gaussian preprocess (64-thread blocks: spread over ~128 SMs) ---
__global__ void __launch_bounds__(64) preprocess_kernel(
                                  const float* __restrict__ pws,
                                  const float* __restrict__ shs,
                                  const float* __restrict__ alphas_raw,
                                  const float* __restrict__ scales_raw,
                                  const float* __restrict__ rots_raw,
                                  const float* __restrict__ Rcw,
                                  const float* __restrict__ tcw,
                                  const float* __restrict__ intr,
                                  float* __restrict__ areas)
{
    int n = blockIdx.x * blockDim.x + threadIdx.x;
    if (n >= NG) return;

    const float fx = intr[0], fy = intr[1], cx = intr[2], cy = intr[3];
    const float R00 = Rcw[0], R01 = Rcw[1], R02 = Rcw[2];
    const float R10 = Rcw[3], R11 = Rcw[4], R12 = Rcw[5];
    const float R20 = Rcw[6], R21 = Rcw[7], R22 = Rcw[8];
    const float t0 = tcw[0], t1 = tcw[1], t2 = tcw[2];

    // vectorized inputs (kernel is load-latency-bound)
    float shv[48];
    {
        const float4* sh4 = (const float4*)(shs + n * 48);
#pragma unroll
        for (int i = 0; i < 12; i++) {
            const float4 v = sh4[i];
            shv[i*4+0] = v.x; shv[i*4+1] = v.y; shv[i*4+2] = v.z; shv[i*4+3] = v.w;
        }
    }
    const float4 q4 = ((const float4*)rots_raw)[n];
    const float pwx = pws[3*n+0], pwy = pws[3*n+1], pwz = pws[3*n+2];

    // camera-space point
    const float pcx = R00*pwx + R01*pwy + R02*pwz + t0;
    const float pcy = R10*pwx + R11*pwy + R12*pwz + t1;
    const float pcz = R20*pwx + R21*pwy + R22*pwz + t2;
    const float depth = pcz;
    const float zs = (depth > 0.2f) ? depth : 1.0f;
    const float iz = 1.0f / zs;

    const float ux = fx * pcx * iz + cx;
    const float uy = fy * pcy * iz + cy;

    // activations (fast-math: rel err ~1e-6, well inside 1e-3 budget)
    const float alpha = 1.0f / (1.0f + __expf(-alphas_raw[n]));
    const float sx = __expf(scales_raw[3*n+0]);
    const float sy = __expf(scales_raw[3*n+1]);
    const float sz = __expf(scales_raw[3*n+2]);

    float qw = q4.x, qx = q4.y, qy = q4.z, qz = q4.w;
    {
        const float qi = rsqrtf(qw*qw + qx*qx + qy*qy + qz*qz);
        qw *= qi; qx *= qi; qy *= qi; qz *= qi;
    }
    // rotation matrix
    const float r00 = 1.0f - 2.0f*(qy*qy + qz*qz), r01 = 2.0f*(qx*qy - qw*qz), r02 = 2.0f*(qx*qz + qw*qy);
    const float r10 = 2.0f*(qx*qy + qw*qz), r11 = 1.0f - 2.0f*(qx*qx + qz*qz), r12 = 2.0f*(qy*qz - qw*qx);
    const float r20 = 2.0f*(qx*qz - qw*qy), r21 = 2.0f*(qy*qz + qw*qx), r22 = 1.0f - 2.0f*(qx*qx + qy*qy);

    // M = R * diag(scales); cov3d = M M^T (symmetric 6)
    const float m00 = r00*sx, m01 = r01*sy, m02 = r02*sz;
    const float m10 = r10*sx, m11 = r11*sy, m12 = r12*sz;
    const float m20 = r20*sx, m21 = r21*sy, m22 = r22*sz;
    const float V00 = m00*m00 + m01*m01 + m02*m02;
    const float V01 = m00*m10 + m01*m11 + m02*m12;
    const float V02 = m00*m20 + m01*m21 + m02*m22;
    const float V11 = m10*m10 + m11*m11 + m12*m12;
    const float V12 = m10*m20 + m11*m21 + m12*m22;
    const float V22 = m20*m20 + m21*m21 + m22*m22;

    // Jacobian and T = J @ Rcw
    const float tanfx = WW / (2.0f * fx);
    const float tanfy = HH / (2.0f * fy);
    const float xn = pcx * iz, yn = pcy * iz;
    const float txl = fminf(fmaxf(xn, -1.3f*tanfx), 1.3f*tanfx) * zs;
    const float tyl = fminf(fmaxf(yn, -1.3f*tanfy), 1.3f*tanfy) * zs;
    const float iz2 = iz * iz;
    const float J00 = fx * iz, J02 = -fx * txl * iz2;
    const float J11 = fy * iz, J12 = -fy * tyl * iz2;
    const float T00 = J00*R00 + J02*R20;
    const float T01 = J00*R01 + J02*R21;
    const float T02 = J00*R02 + J02*R22;
    const float T10 = J11*R10 + J12*R20;
    const float T11 = J11*R11 + J12*R21;
    const float T12 = J11*R12 + J12*R22;

    // cov2d = T V T^T + 0.3 I
    const float v0 = V00*T00 + V01*T01 + V02*T02;
    const float v1 = V01*T00 + V11*T01 + V12*T02;
    const float v2 = V02*T00 + V12*T01 + V22*T02;
    const float w0 = V00*T10 + V01*T11 + V02*T12;
    const float w1 = V01*T10 + V11*T11 + V12*T12;
    const float w2 = V02*T10 + V12*T11 + V22*T12;
    const float a = T00*v0 + T01*v1 + T02*v2 + 0.3f;
    const float b = T00*w0 + T01*w1 + T02*w2;
    const float c = T10*w0 + T11*w1 + T12*w2 + 0.3f;

    const float det = a*c - b*b;
    const bool valid = (depth > 0.2f) && (det > 0.0f);
    const float det_s = valid ? det : 1.0f;
    const float invd = 1.0f / det_s;
    const float ca = c * invd;
    const float cb = -b * invd;
    const float cc = a * invd;

    const float mid = 0.5f * (a + c);
    const float lam = mid + sqrtf(fmaxf(mid*mid - det, 0.1f));
    const float radius = valid ? ceilf(3.0f * sqrtf(lam)) : 0.0f;
    areas[2*n+0] = radius;
    areas[2*n+1] = radius;

    // view direction (twc = -Rcw^T tcw)
    const float twcx = -(R00*t0 + R10*t1 + R20*t2);
    const float twcy = -(R01*t0 + R11*t1 + R21*t2);
    const float twcz = -(R02*t0 + R12*t1 + R22*t2);
    float dxn = pwx - twcx, dyn = pwy - twcy, dzn = pwz - twcz;
    const float dinv = rsqrtf(dxn*dxn + dyn*dyn + dzn*dzn);
    const float X = dxn*dinv, Y = dyn*dinv, Z = dzn*dinv;
    const float XX = X*X, YY = Y*Y, ZZ = Z*Z, XY = X*Y, YZ = Y*Z, XZ = X*Z;

    float col[3];
#pragma unroll
    for (int ch = 0; ch < 3; ch++) {
        float res =  0.28209479177387814f * shv[0*3+ch];
        res += -0.4886025119029199f  * Y * shv[1*3+ch];
        res +=  0.4886025119029199f  * Z * shv[2*3+ch];
        res += -0.4886025119029199f  * X * shv[3*3+ch];
        res +=  1.0925484305920792f  * XY * shv[4*3+ch];
        res += -1.0925484305920792f  * YZ * shv[5*3+ch];
        res +=  0.31539156525252005f * (2.0f*ZZ - XX - YY) * shv[6*3+ch];
        res += -1.0925484305920792f  * XZ * shv[7*3+ch];
        res +=  0.5462742152960396f  * (XX - YY) * shv[8*3+ch];
        res += -0.5900435899266435f  * Y * (3.0f*XX - YY) * shv[9*3+ch];
        res +=  2.890611442640554f   * XY * Z * shv[10*3+ch];
        res += -0.4570457994644658f  * Y * (4.0f*ZZ - XX - YY) * shv[11*3+ch];
        res +=  0.3731763325901154f  * Z * (2.0f*ZZ - 3.0f*XX - 3.0f*YY) * shv[12*3+ch];
        res += -0.4570457994644658f  * X * (4.0f*ZZ - XX - YY) * shv[13*3+ch];
        res +=  1.445305721320277f   * Z * (XX - YY) * shv[14*3+ch];
        res += -0.5900435899266435f  * X * (XX - 3.0f*YY) * shv[15*3+ch];
        col[ch] = fmaxf(res + 0.5f, 0.0f);
    }

    // conservative support half-extents: alp >= 1/255 requires Q <= ln(255*alpha)
    const float tthr = __logf(255.0f * alpha);
    float ex, ey;
    if (valid && tthr > 0.0f) {
        ex = sqrtf(2.0f * tthr * a) + 1.0f;   // +1px safety margin
        ey = sqrtf(2.0f * tthr * c) + 1.0f;
    } else {
        ex = -1e30f; ey = -1e30f;             // never overlaps any tile
    }

    g_pre[n*3+0] = make_float4(ux, uy, ca, cb);
    g_pre[n*3+1] = make_float4(cc, alpha, ex, ey);
    g_pre[n*3+2] = make_float4(col[0], col[1], col[2], 0.0f);

    // sortable key: float -> monotone uint, packed with index for a unique stable key
    unsigned ub = __float_as_uint(depth);
    ub = (ub & 0x80000000u) ? ~ub : (ub | 0x80000000u);
    g_bufA[n] = ((unsigned long long)ub << 16) | (unsigned)n;
}

// ---------------- 2. depth argsort: single-CTA 4x8-bit LSD radix, fully in-smem --------
// 1024 threads = 32 warps, 8 elements/thread. Key = bits [16,48) of the packed u64.
// Staging (48-bit keys split u32+u16) stays resident in smem between passes, aliased
// over the histogram region. Mid-phases (totals / offset-convert) run on ALL 1024
// threads as (quarter, digit) pairs: serial depth 32 -> 8, utilization 4x.
__global__ void __launch_bounds__(1024) sort_kernel()
{
    __shared__ __align__(16) unsigned char sbuf[49152];     // 48KB union
    unsigned*       hist  = (unsigned*)sbuf;                // [32][256]  (hist phase)
    unsigned*       aux   = (unsigned*)(sbuf + 32768);      // dbase[256] + partial[4][256]
    unsigned*       keyA  = (unsigned*)sbuf;                // [8192] low 32 (staging phase)
    unsigned short* keyB  = (unsigned short*)(sbuf + 32768);// [8192] high 16 (staging phase)
    unsigned* dbase   = aux;                                // [256]
    unsigned* partial = aux + 256;                          // [4][256]

    const int tid  = threadIdx.x;
    const int wid  = tid >> 5;
    const int lane = tid & 31;
    const int q    = tid >> 8;     // quarter (0..3) = warps q*8..q*8+7
    const int g    = tid & 255;    // digit
    const unsigned FULL = 0xffffffffu;

#pragma unroll
    for (int pass = 0; pass < 4; pass++) {
        const int shift = 16 + 8 * pass;

        // load 8 elements into registers (from global on pass 0, staging after)
        unsigned long long v[8];
        int d[8];
#pragma unroll
        for (int s = 0; s < 8; s++) {
            const int i = wid * 256 + s * 32 + lane;
            if (pass == 0) v[s] = g_bufA[i];
            else           v[s] = ((unsigned long long)keyB[i] << 32) | keyA[i];
            d[s] = (int)((v[s] >> shift) & 255u);
        }
        __syncthreads();              // staging fully read before hist zeroing clobbers it

        // zero per-warp histograms (first 32KB only)
        for (int i = tid; i < 32 * 256; i += 1024)
            hist[i] = 0u;
        __syncthreads();

        // per-warp histogram (private row: no cross-warp contention)
#pragma unroll
        for (int s = 0; s < 8; s++)
            atomicAdd(&hist[wid * 256 + d[s]], 1u);
        __syncthreads();

        // quarter partial sums: thread (q,g) sums its 8 warps (independent loads, MLP=8)
        {
            unsigned p = 0;
#pragma unroll
            for (int w8 = 0; w8 < 8; w8++) p += hist[(q * 8 + w8) * 256 + g];
            partial[q * 256 + g] = p;
        }
        __syncthreads();

        // digit totals
        if (tid < 256)
            dbase[tid] = partial[tid] + partial[256 + tid] + partial[512 + tid] + partial[768 + tid];
        __syncthreads();

        // exclusive scan of 256 digit totals (warp 0, 8 values per lane)
        if (tid < 32) {
            unsigned x[8], e[8], s = 0;
#pragma unroll
            for (int k = 0; k < 8; k++) { x[k] = dbase[tid * 8 + k]; e[k] = s; s += x[k]; }
            unsigned inc = s;
#pragma unroll
            for (int off = 1; off < 32; off <<= 1) {
                unsigned nval = __shfl_up_sync(FULL, inc, off);
                if (lane >= off) inc += nval;
            }
            const unsigned wexcl = inc - s;
#pragma unroll
            for (int k = 0; k < 8; k++) dbase[tid * 8 + k] = wexcl + e[k];
        }
        __syncthreads();

        // convert per-warp counts into absolute running start offsets (warp-major stable)
        // thread (q,g): start = digit base + partials of earlier quarters, then 8-deep walk
        {
            unsigned run = dbase[g];
#pragma unroll
            for (int qq = 0; qq < 3; qq++) if (qq < q) run += partial[qq * 256 + g];
#pragma unroll
            for (int w8 = 0; w8 < 8; w8++) {
                const int h = (q * 8 + w8) * 256 + g;
                const unsigned tmp = hist[h];
                hist[h] = run;
                run += tmp;
            }
        }
        __syncthreads();

        // phase A: compute all scatter positions into registers (consumes hist)
        unsigned pos[8];
#pragma unroll
        for (int s = 0; s < 8; s++) {
            const unsigned peers  = __match_any_sync(FULL, d[s]);
            const unsigned rank   = __popc(peers & ((1u << lane) - 1u));
            const int      leader = __ffs(peers) - 1;
            unsigned base_o = 0;
            if (lane == leader) base_o = hist[wid * 256 + d[s]];
            base_o = __shfl_sync(FULL, base_o, leader);
            pos[s] = base_o + rank;
            if (lane == leader) hist[wid * 256 + d[s]] = base_o + __popc(peers);
        }
        __syncthreads();              // hist dead; staging writes may now clobber it

        // phase B: scatter into smem staging (keyA/keyB alias hist+aux)
#pragma unroll
        for (int s = 0; s < 8; s++) {
            keyA[pos[s]] = (unsigned)v[s];
            keyB[pos[s]] = (unsigned short)(v[s] >> 32);
        }
        __syncthreads();
    }

    // sorted order: original index is low 16 bits of the packed key
    for (int i = tid; i < NG; i += 1024)
        g_order[i] = (int)(keyA[i] & 0xFFFFu);
}

// ---------------- 3. gather into sorted order ----------------
__global__ void gather_kernel()
{
    const int s = blockIdx.x * blockDim.x + threadIdx.x;
    if (s < NG) {
        const int g = g_order[s];
        const float4 p0 = g_pre[g*3+0];
        const float4 p1 = g_pre[g*3+1];
        g_pack[s*3+0] = p0;
        g_pack[s*3+1] = p1;
        g_pack[s*3+2] = g_pre[g*3+2];
        g_cull[s] = make_float4(p0.x, p0.y, p1.z, p1.w);   // (ux, uy, ex, ey)
    }
}

// ---------------- 4. segmented tile binning: grid (32 tile-groups, 8 segments) --------
__global__ void __launch_bounds__(256) binning_kernel()
{
    __shared__ float4 scv[256];
    const int tid  = threadIdx.x;
    const int wid  = tid >> 5;
    const int lane = tid & 31;
    const int t    = blockIdx.x * 8 + wid;         // tile id (0..255)
    const int seg  = blockIdx.y;                   // segment id (0..7)
    const float tx0 = (float)((t & 15) * 16), tx1 = tx0 + 15.0f;
    const float ty0 = (float)((t >> 4) * 16), ty1 = ty0 + 15.0f;

    unsigned short* lst = g_list + t * NG + seg * SEGSZ;
    int cnt = 0;
    for (int base = seg * SEGSZ; base < (seg + 1) * SEGSZ; base += 256) {
        __syncthreads();                           // protect scv reuse across chunks
        scv[tid] = g_cull[base + tid];             // coalesced, latency hidden across warps
        __syncthreads();
#pragma unroll
        for (int j = 0; j < 8; j++) {
            const float4 cv = scv[j * 32 + lane];
            const bool keep = (cv.x - cv.z <= tx1) && (cv.x + cv.z >= tx0) &&
                              (cv.y - cv.w <= ty1) && (cv.y + cv.w >= ty0);
            const unsigned m = __ballot_sync(0xffffffffu, keep);
            if (keep)
                lst[cnt + __popc(m & ((1u << lane) - 1u))] =
                    (unsigned short)(base + j * 32 + lane);
            cnt += __popc(m);
        }
    }
    if (lane == 0) g_cnt[seg * 256 + t] = cnt;
}

// ---------------- 5. tiled compositing, virtual-concatenated segment lists -------------
__global__ void __launch_bounds__(256) render_kernel(float* __restrict__ out)
{
    __shared__ float4 s0[256];
    __shared__ float4 s1[256];
    __shared__ float  s2[256];
    __shared__ int    pre[NSEG + 1];

    const int tid = threadIdx.x;
    const int t = blockIdx.x;                       // tile id
    const int x = (t & 15) * 16 + (tid & 15);
    const int y = (t >> 4) * 16 + (tid >> 4);
    const float px = (float)x, py = (float)y;

    const unsigned short* lstT = g_list + t * NG;

    // segment-count prefix (virtual concatenation of the 8 depth-ordered sublists)
    if (tid == 0) {
        int acc = 0;
        pre[0] = 0;
#pragma unroll
        for (int s = 0; s < NSEG; s++) { acc += g_cnt[s * 256 + t]; pre[s + 1] = acc; }
    }
    __syncthreads();
    const int nlist = pre[NSEG];

    float T = 1.0f, ar = 0.0f, ag = 0.0f, ab = 0.0f;
    int done = 0;

    for (int base = 0; base < nlist; base += 256) {
        const int n = min(256, nlist - base);
        if (tid < n) {
            const int i = base + tid;
            int seg = 0;
#pragma unroll
            for (int s = 0; s < NSEG - 1; s++) if (i >= pre[s + 1]) seg = s + 1;
            const int idx = (int)lstT[seg * SEGSZ + (i - pre[seg])];
            const float4 p0 = g_pack[idx*3+0];      // (ux, uy, ca, cb)
            const float4 p1 = g_pack[idx*3+1];      // (cc, alpha, ex, ey)
            const float4 p2 = g_pack[idx*3+2];      // (r, g, b, 0)
            s0[tid] = p0;
            s1[tid] = make_float4(p1.x, p1.y, p2.x, p2.y);   // (cc, alpha, r, g)
            s2[tid] = p2.z;                                  // b
        }
        __syncthreads();                            // compaction visible before reads

        if (!done) {
            for (int i = 0; i < n; i++) {
                const float4 q0 = s0[i];
                const float4 q1 = s1[i];
                const float dx = px - q0.x;
                const float dy = py - q0.y;
                const float pw = -0.5f*(q0.z*dx*dx + q1.x*dy*dy) - q0.w*dx*dy;
                if (pw > 0.0f) continue;
                const float alp = fminf(0.99f, q1.y * __expf(pw));
                if (alp < (1.0f/255.0f)) continue;
                const float wgt = alp * T;
                ar += wgt * q1.z;
                ag += wgt * q1.w;
                ab += wgt * s2[i];
                T *= (1.0f - alp);
                if (T <= 1e-4f) { done = 1; break; }
            }
        }
        // consensus early-exit; also orders this chunk's reads before next chunk's writes
        if (__syncthreads_and(done)) break;
    }

    const int p = y * WW + x;
    out[p]         = ar;
    out[HWP + p]   = ag;
    out[2*HWP + p] = ab;
}

// ---------------- launch ----------------
extern "C" void kernel_launch(void* const* d_in, const int* in_sizes, int n_in,
                              void* d_out, int out_size)
{
    const float* pws        = (const float*)d_in[0];
    const float* shs        = (const float*)d_in[1];
    const float* alphas_raw = (const float*)d_in[2];
    const float* scales_raw = (const float*)d_in[3];
    const float* rots_raw   = (const float*)d_in[4];
    // d_in[5] = us (forward no-op)
    const float* Rcw        = (const float*)d_in[6];
    const float* tcw        = (const float*)d_in[7];
    const float* intr       = (const float*)d_in[8];
    float* out = (float*)d_out;

    preprocess_kernel<<<NG / 64, 64>>>(pws, shs, alphas_raw, scales_raw, rots_raw,
                                       Rcw, tcw, intr, out + 3 * HWP);
    sort_kernel<<<1, 1024>>>();
    gather_kernel<<<(NG + 255) / 256, 256>>>();
    binning_kernel<<<dim3(32, NSEG), 256>>>();
    render_kernel<<<256, 256>>>(out);
}